// round 5
// baseline (speedup 1.0000x reference)
#include <cuda_runtime.h>
#include <cuda_bf16.h>
#include <math_constants.h>
#include <cstdint>

#define Bc 2
#define Tc 2048
#define Dc 1024
#define Hc 16
#define HDc 64
#define Mc (Bc*Tc)

#define KTOT 3072          // tripled K for split-bf16 3-product GEMM
#define BM 128
#define BN 256
#define BK 32
#define NK (KTOT/BK)       // 96
#define LDS_ROW 40
#define A_STG (BM*LDS_ROW*2)              // 10240
#define B_STG (BN*LDS_ROW*2)              // 20480
#define STG_BYTES (A_STG+B_STG)           // 30720
#define STAGES 3
#define SMEM_DYN (STAGES*STG_BYTES)       // 92160

// attention tiling
#define AT_M 128
#define LDSA 200
#define LDV  72
#define SG_BYTES_A (128*LDSA*2)
#define K2STG (64*LDSA*2)
#define VTSTG (128*LDV*2)
#define ASMEM (SG_BYTES_A + 2*K2STG + 2*VTSTG)  // 139264

// ---------------- scratch (device globals; no runtime allocation) ----------
__device__ __align__(16) float g_q[Bc*Hc*Tc*HDc];      // (b,h,t,hd) fp32
__device__ __align__(16) float g_ksum[Bc*Hc*HDc];
__device__ __align__(16) float g_gdiag[Hc*HDc];
__device__ __align__(16) float g_bqkv[3*Dc];
__device__ __align__(16) __nv_bfloat16 g_x2[Mc*KTOT];        // [hi|hi|lo] of x
__device__ __align__(16) __nv_bfloat16 g_w2[4][Dc*KTOT];     // [hi|lo|hi] W (q,k,v,o rows contiguous)
__device__ __align__(16) __nv_bfloat16 g_o2[Mc*KTOT];        // [hi|hi|lo] of attn output
__device__ __align__(16) __nv_bfloat16 g_k2[Bc*Hc*Tc*192];   // [hi|lo|hi] key rows
__device__ __align__(16) __nv_bfloat16 g_sg2[Bc*Hc*Tc*192];  // [hi|hi|lo] Sg rows
__device__ __align__(16) __nv_bfloat16 g_v2t[Bc*Hc*2*HDc*Tc];// [bh][hi/lo][d][t]

// ---------------- PTX helpers ----------------------------------------------
__device__ __forceinline__ uint32_t smem_u32(const void* p) {
    uint32_t a;
    asm("{ .reg .u64 t; cvta.to.shared.u64 t, %1; cvt.u32.u64 %0, t; }" : "=r"(a) : "l"(p));
    return a;
}
#define CP_ASYNC16(sm, gm) \
    asm volatile("cp.async.cg.shared.global [%0], [%1], 16;" :: "r"(sm), "l"(gm))
#define CP_COMMIT() asm volatile("cp.async.commit_group;" ::: "memory")
#define CP_WAIT(n)  asm volatile("cp.async.wait_group %0;" :: "n"(n) : "memory")

__device__ __forceinline__ void ldsm_x4(uint32_t& r0, uint32_t& r1,
                                        uint32_t& r2, uint32_t& r3, uint32_t addr) {
    asm volatile("ldmatrix.sync.aligned.m8n8.x4.shared.b16 {%0,%1,%2,%3}, [%4];"
                 : "=r"(r0), "=r"(r1), "=r"(r2), "=r"(r3) : "r"(addr));
}
__device__ __forceinline__ void mma16816(float* c, const uint32_t* a, const uint32_t* b) {
    asm volatile(
        "mma.sync.aligned.m16n8k16.row.col.f32.bf16.bf16.f32 "
        "{%0,%1,%2,%3}, {%4,%5,%6,%7}, {%8,%9}, {%0,%1,%2,%3};"
        : "+f"(c[0]), "+f"(c[1]), "+f"(c[2]), "+f"(c[3])
        : "r"(a[0]), "r"(a[1]), "r"(a[2]), "r"(a[3]), "r"(b[0]), "r"(b[1]));
}
__device__ __forceinline__ uint32_t pkbf(float lo, float hi) {
    uint32_t r;
    asm("cvt.rn.bf16x2.f32 %0, %1, %2;" : "=r"(r) : "f"(hi), "f"(lo));
    return r;
}
__device__ __forceinline__ float bfr(float x) {
    return __bfloat162float(__float2bfloat16(x));
}

// ---------------------------------------------------------------------------
// split fp32 -> bf16 triple. mode 0 (A): [hi|hi|lo]; mode 1 (B): [hi|lo|hi].
// ---------------------------------------------------------------------------
__global__ void split_kernel(const float* __restrict__ src,
                             __nv_bfloat16* __restrict__ dst, int rows, int mode) {
    int idx = blockIdx.x * blockDim.x + threadIdx.x;
    if (idx >= rows * (Dc/2)) return;
    float2 v = ((const float2*)src)[idx];
    int r = idx / (Dc/2), c2 = idx % (Dc/2);
    __nv_bfloat162 hi, lo;
    hi.x = __float2bfloat16(v.x); hi.y = __float2bfloat16(v.y);
    lo.x = __float2bfloat16(v.x - __bfloat162float(hi.x));
    lo.y = __float2bfloat16(v.y - __bfloat162float(hi.y));
    __nv_bfloat162* d = (__nv_bfloat162*)(dst + (size_t)r * KTOT);
    if (mode == 0) { d[c2] = hi; d[512 + c2] = hi; d[1024 + c2] = lo; }
    else           { d[c2] = hi; d[512 + c2] = lo; d[1024 + c2] = hi; }
}

__global__ void bias_concat(const float* __restrict__ bq, const float* __restrict__ bk,
                            const float* __restrict__ bv) {
    int i = blockIdx.x * blockDim.x + threadIdx.x;
    if (i >= 3 * Dc) return;
    g_bqkv[i] = (i < Dc) ? bq[i] : (i < 2*Dc) ? bk[i - Dc] : bv[i - 2*Dc];
}

// ---------------------------------------------------------------------------
// mma.sync bf16 GEMM, tile 128x256, warp tile 64x64, BK=32, 3-stage cp.async,
// single sync per K-iteration.
// mode 0: fused QKV over N=3072 (routing by n0>>10: q fp32 / k triple / v planes)
// mode 1: final projection -> Yext[4096,1024]
// ---------------------------------------------------------------------------
__global__ __launch_bounds__(256)
void gemm_tc(const __nv_bfloat16* __restrict__ A2, const __nv_bfloat16* __restrict__ W2,
             const float* __restrict__ bias, float* __restrict__ Yext, int mode)
{
    extern __shared__ __align__(16) char dsmem[];
    uint32_t base = smem_u32(dsmem);

    int tid = threadIdx.x, wid = tid >> 5, lane = tid & 31;
    int wm = wid & 1, wn = wid >> 1;               // 2x4 warp grid, warp 64x64
    int m0 = blockIdx.x * BM, n0 = blockIdx.y * BN;

    const __nv_bfloat16* gA = A2 + (size_t)m0 * KTOT;
    const __nv_bfloat16* gW = W2 + (size_t)n0 * KTOT;

    auto load_chunk = [&](int c) {
        uint32_t sa = base + (c % STAGES) * STG_BYTES;
        uint32_t sb = sa + A_STG;
        int k0 = c * BK;
#pragma unroll
        for (int it = 0; it < 2; it++) {           // A: 512 x 16B
            int ch = tid + it * 256;
            int r = ch >> 2, off = (ch & 3) * 8;
            CP_ASYNC16(sa + r * (LDS_ROW*2) + off * 2,
                       (const char*)(gA + (size_t)r * KTOT + k0 + off));
        }
#pragma unroll
        for (int it = 0; it < 4; it++) {           // B: 1024 x 16B
            int ch = tid + it * 256;
            int r = ch >> 2, off = (ch & 3) * 8;
            CP_ASYNC16(sb + r * (LDS_ROW*2) + off * 2,
                       (const char*)(gW + (size_t)r * KTOT + k0 + off));
        }
        CP_COMMIT();
    };

    float acc[4][8][4];
#pragma unroll
    for (int i = 0; i < 4; i++)
#pragma unroll
        for (int j = 0; j < 8; j++)
#pragma unroll
            for (int l = 0; l < 4; l++) acc[i][j][l] = 0.f;

    load_chunk(0);
    load_chunk(1);

    int a_row = wm * 64 + (lane & 15);
    int a_col8 = (lane >> 4) * 8;
    int b_row = wn * 64 + (lane & 7) + ((lane >> 4) << 3);
    int b_col8 = ((lane >> 3) & 1) * 8;

#pragma unroll 1
    for (int i = 0; i < NK; i++) {
        CP_WAIT(1);
        __syncthreads();
        if (i + 2 < NK) load_chunk(i + 2);

        uint32_t sa = base + (i % STAGES) * STG_BYTES;
        uint32_t sb = sa + A_STG;
#pragma unroll
        for (int kk = 0; kk < 2; kk++) {
            uint32_t a[4][4], b[8][2];
#pragma unroll
            for (int mf = 0; mf < 4; mf++)
                ldsm_x4(a[mf][0], a[mf][1], a[mf][2], a[mf][3],
                        sa + ((a_row + mf*16) * LDS_ROW + kk*16 + a_col8) * 2);
#pragma unroll
            for (int np = 0; np < 4; np++)
                ldsm_x4(b[2*np][0], b[2*np][1], b[2*np+1][0], b[2*np+1][1],
                        sb + ((b_row + np*16) * LDS_ROW + kk*16 + b_col8) * 2);
#pragma unroll
            for (int mf = 0; mf < 4; mf++)
#pragma unroll
                for (int nf = 0; nf < 8; nf++)
                    mma16816(acc[mf][nf], a[mf], b[nf]);
        }
    }

    int proj = n0 >> 10;                 // constant per CTA (256 | 1024)
#pragma unroll
    for (int mf = 0; mf < 4; mf++) {
#pragma unroll
        for (int nf = 0; nf < 8; nf++) {
            int m = m0 + wm*64 + mf*16 + (lane >> 2);
            int n = n0 + wn*64 + nf*8 + 2*(lane & 3);
            float b0 = bias[n], b1 = bias[n+1];
#pragma unroll
            for (int half = 0; half < 2; half++) {
                int mm = m + half * 8;
                float v0 = acc[mf][nf][half*2+0] + b0;
                float v1 = acc[mf][nf][half*2+1] + b1;
                int bb = mm >> 11, t = mm & 2047;
                int nn = n & 1023;
                int h = nn >> 6, d = nn & 63;
                int bh = bb * Hc + h;
                if (mode == 1) {
                    *(float2*)(Yext + (size_t)mm * Dc + n) = make_float2(v0, v1);
                } else if (proj == 0) {
                    *(float2*)(g_q + ((size_t)bh * Tc + t) * HDc + d) =
                        make_float2(v0, v1);
                } else if (proj == 1) {
                    __nv_bfloat16 h0 = __float2bfloat16(v0);
                    __nv_bfloat16 l0 = __float2bfloat16(v0 - __bfloat162float(h0));
                    __nv_bfloat16 h1 = __float2bfloat16(v1);
                    __nv_bfloat16 l1 = __float2bfloat16(v1 - __bfloat162float(h1));
                    __nv_bfloat16* row = g_k2 + ((size_t)bh * Tc + t) * 192;
                    row[d] = h0;   row[d+1] = h1;
                    row[64+d] = l0; row[64+d+1] = l1;
                    row[128+d] = h0; row[128+d+1] = h1;
                } else {
                    __nv_bfloat16 h0 = __float2bfloat16(v0);
                    __nv_bfloat16 l0 = __float2bfloat16(v0 - __bfloat162float(h0));
                    __nv_bfloat16 h1 = __float2bfloat16(v1);
                    __nv_bfloat16 l1 = __float2bfloat16(v1 - __bfloat162float(h1));
                    __nv_bfloat16* pbase = g_v2t + (size_t)bh * 2 * HDc * Tc;
                    pbase[(size_t)d * Tc + t] = h0;
                    pbase[(size_t)(d+1) * Tc + t] = h1;
                    pbase[(size_t)(HDc + d) * Tc + t] = l0;
                    pbase[(size_t)(HDc + d+1) * Tc + t] = l1;
                }
            }
        }
    }
}

// ---------------------------------------------------------------------------
__global__ void gdiag_kernel(const float* __restrict__ A,
                             const float* __restrict__ log_lambda) {
    int i = blockIdx.x * blockDim.x + threadIdx.x;
    if (i >= Hc * HDc) return;
    int h = i >> 6, d = i & 63;
    float s = expf(log_lambda[h]);
#pragma unroll
    for (int r = 0; r < 16; r++) {
        float a = A[(h * 16 + r) * HDc + d];
        s = fmaf(a, a, s);
    }
    g_gdiag[i] = s;
}

__global__ __launch_bounds__(256) void ksum2_kernel() {
    __shared__ float red[256];
    int bh = blockIdx.x;
    int d = threadIdx.x & 63, chunk = threadIdx.x >> 6;
    const __nv_bfloat16* base = g_k2 + (size_t)bh * Tc * 192;
    float s = 0.f;
    for (int t = chunk * 512; t < (chunk + 1) * 512; t++) {
        const __nv_bfloat16* row = base + (size_t)t * 192;
        s += __bfloat162float(row[d]) + __bfloat162float(row[64 + d]);
    }
    red[threadIdx.x] = s;
    __syncthreads();
    if (chunk == 0) {
        float tot = red[d] + red[64+d] + red[128+d] + red[192+d];
        g_ksum[bh * HDc + d] = tot;
    }
}

__global__ void sgprep_kernel() {
    int idx = blockIdx.x * blockDim.x + threadIdx.x;
    if (idx >= Bc*Hc*Tc*HDc) return;
    int bh = idx >> 17;
    int rem = idx & 131071;
    int t = rem >> 6, d = rem & 63;
    float q = g_q[((size_t)bh * Tc + t) * HDc + d];
    float sg = (2048.0f * q - g_ksum[bh * HDc + d]) * g_gdiag[(bh & 15) * HDc + d];
    __nv_bfloat16 hi = __float2bfloat16(sg);
    __nv_bfloat16 lo = __float2bfloat16(sg - __bfloat162float(hi));
    __nv_bfloat16* row = g_sg2 + ((size_t)bh * Tc + t) * 192;
    row[d] = hi; row[64 + d] = hi; row[128 + d] = lo;
}

// ---------------------------------------------------------------------------
// Tensor-core flash attention; epilogue writes split triple g_o2 directly.
// ---------------------------------------------------------------------------
__global__ __launch_bounds__(256, 1)
void attn_tc() {
    extern __shared__ __align__(16) char asmem[];
    uint32_t sgs = smem_u32(asmem);
    uint32_t k2s = sgs + SG_BYTES_A;
    uint32_t vts = k2s + 2 * K2STG;

    int tid = threadIdx.x, wid = tid >> 5, lane = tid & 31;
    int bh = blockIdx.y, h = bh & 15, b = bh >> 4;
    int q0 = blockIdx.x * AT_M;

    const __nv_bfloat16* sg_g = g_sg2 + ((size_t)bh * Tc + q0) * 192;
    const __nv_bfloat16* k_g  = g_k2  + (size_t)bh * Tc * 192;
    const __nv_bfloat16* v_g  = g_v2t + (size_t)bh * 2 * HDc * Tc;

#pragma unroll
    for (int it = 0; it < 12; it++) {
        int id = tid + it * 256;
        int r = id / 24, c = id % 24;
        CP_ASYNC16(sgs + r * (LDSA*2) + c * 16, (const char*)(sg_g + (size_t)r * 192 + c * 8));
    }
    CP_COMMIT();

    auto load_tile = [&](int ti) {
        int st = ti & 1;
        int j0 = ti * 64;
        uint32_t kd = k2s + st * K2STG;
        uint32_t vd = vts + st * VTSTG;
#pragma unroll
        for (int it = 0; it < 6; it++) {
            int id = tid + it * 256;
            int r = id / 24, c = id % 24;
            CP_ASYNC16(kd + r * (LDSA*2) + c * 16,
                       (const char*)(k_g + (size_t)(j0 + r) * 192 + c * 8));
        }
#pragma unroll
        for (int it = 0; it < 4; it++) {
            int id = tid + it * 256;
            int r = id >> 3, c = id & 7;
            CP_ASYNC16(vd + r * (LDV*2) + c * 16,
                       (const char*)(v_g + (size_t)r * Tc + j0 + c * 8));
        }
        CP_COMMIT();
    };

    load_tile(0);
    CP_WAIT(1);
    __syncthreads();

    uint32_t aq[12][4];
    {
        int arow = wid * 16 + (lane & 15);
        int acol = (lane >> 4) * 8;
#pragma unroll
        for (int kc = 0; kc < 12; kc++)
            ldsm_x4(aq[kc][0], aq[kc][1], aq[kc][2], aq[kc][3],
                    sgs + (arow * LDSA + kc * 16 + acol) * 2);
    }

    float o_acc[8][4];
#pragma unroll
    for (int nf = 0; nf < 8; nf++)
#pragma unroll
        for (int l = 0; l < 4; l++) o_acc[nf][l] = 0.f;
    float m0 = -CUDART_INF_F, m1 = -CUDART_INF_F, l0 = 0.f, l1 = 0.f;

    int brow = (lane & 7) + ((lane >> 4) << 3);
    int bcol8 = ((lane >> 3) & 1) * 8;

#pragma unroll 1
    for (int ti = 0; ti < 32; ti++) {
        if (ti + 1 < 32) { load_tile(ti + 1); CP_WAIT(1); }
        else CP_WAIT(0);
        __syncthreads();
        int st = ti & 1;
        uint32_t kd = k2s + st * K2STG;
        uint32_t vd = vts + st * VTSTG;

        float s[8][4];
#pragma unroll
        for (int nf = 0; nf < 8; nf++)
#pragma unroll
            for (int l = 0; l < 4; l++) s[nf][l] = 0.f;
#pragma unroll
        for (int kc = 0; kc < 12; kc++) {
            uint32_t bq[8][2];
#pragma unroll
            for (int np = 0; np < 4; np++)
                ldsm_x4(bq[2*np][0], bq[2*np][1], bq[2*np+1][0], bq[2*np+1][1],
                        kd + ((np*16 + brow) * LDSA + kc*16 + bcol8) * 2);
#pragma unroll
            for (int nf = 0; nf < 8; nf++)
                mma16816(s[nf], aq[kc], bq[nf]);
        }

        float rm0 = -CUDART_INF_F, rm1 = -CUDART_INF_F;
#pragma unroll
        for (int nf = 0; nf < 8; nf++) {
            rm0 = fmaxf(rm0, fmaxf(s[nf][0], s[nf][1]));
            rm1 = fmaxf(rm1, fmaxf(s[nf][2], s[nf][3]));
        }
        rm0 = fmaxf(rm0, __shfl_xor_sync(0xffffffffu, rm0, 1));
        rm0 = fmaxf(rm0, __shfl_xor_sync(0xffffffffu, rm0, 2));
        rm1 = fmaxf(rm1, __shfl_xor_sync(0xffffffffu, rm1, 1));
        rm1 = fmaxf(rm1, __shfl_xor_sync(0xffffffffu, rm1, 2));
        float mn0 = fmaxf(m0, rm0), mn1 = fmaxf(m1, rm1);
        float sc0 = __expf(m0 - mn0), sc1 = __expf(m1 - mn1);
        m0 = mn0; m1 = mn1;
        float rs0 = 0.f, rs1 = 0.f;
#pragma unroll
        for (int nf = 0; nf < 8; nf++) {
            s[nf][0] = __expf(s[nf][0] - mn0);
            s[nf][1] = __expf(s[nf][1] - mn0);
            s[nf][2] = __expf(s[nf][2] - mn1);
            s[nf][3] = __expf(s[nf][3] - mn1);
            rs0 += s[nf][0] + s[nf][1];
            rs1 += s[nf][2] + s[nf][3];
        }
        rs0 += __shfl_xor_sync(0xffffffffu, rs0, 1);
        rs0 += __shfl_xor_sync(0xffffffffu, rs0, 2);
        rs1 += __shfl_xor_sync(0xffffffffu, rs1, 1);
        rs1 += __shfl_xor_sync(0xffffffffu, rs1, 2);
        l0 = l0 * sc0 + rs0;
        l1 = l1 * sc1 + rs1;
#pragma unroll
        for (int nf = 0; nf < 8; nf++) {
            o_acc[nf][0] *= sc0; o_acc[nf][1] *= sc0;
            o_acc[nf][2] *= sc1; o_acc[nf][3] *= sc1;
        }

        uint32_t Ahi[4][4], Alo[4][4];
#pragma unroll
        for (int kc = 0; kc < 4; kc++) {
            int f0 = 2*kc, f1 = 2*kc + 1;
            float h00 = bfr(s[f0][0]), h01 = bfr(s[f0][1]);
            float h02 = bfr(s[f0][2]), h03 = bfr(s[f0][3]);
            float h10 = bfr(s[f1][0]), h11 = bfr(s[f1][1]);
            float h12 = bfr(s[f1][2]), h13 = bfr(s[f1][3]);
            Ahi[kc][0] = pkbf(h00, h01);
            Ahi[kc][1] = pkbf(h02, h03);
            Ahi[kc][2] = pkbf(h10, h11);
            Ahi[kc][3] = pkbf(h12, h13);
            Alo[kc][0] = pkbf(s[f0][0]-h00, s[f0][1]-h01);
            Alo[kc][1] = pkbf(s[f0][2]-h02, s[f0][3]-h03);
            Alo[kc][2] = pkbf(s[f1][0]-h10, s[f1][1]-h11);
            Alo[kc][3] = pkbf(s[f1][2]-h12, s[f1][3]-h13);
        }

#pragma unroll
        for (int kc = 0; kc < 4; kc++) {
            uint32_t bvh[8][2], bvl[8][2];
#pragma unroll
            for (int np = 0; np < 4; np++) {
                ldsm_x4(bvh[2*np][0], bvh[2*np][1], bvh[2*np+1][0], bvh[2*np+1][1],
                        vd + ((np*16 + brow) * LDV + kc*16 + bcol8) * 2);
                ldsm_x4(bvl[2*np][0], bvl[2*np][1], bvl[2*np+1][0], bvl[2*np+1][1],
                        vd + ((64 + np*16 + brow) * LDV + kc*16 + bcol8) * 2);
            }
#pragma unroll
            for (int nf = 0; nf < 8; nf++) {
                mma16816(o_acc[nf], Ahi[kc], bvh[nf]);
                mma16816(o_acc[nf], Ahi[kc], bvl[nf]);
                mma16816(o_acc[nf], Alo[kc], bvh[nf]);
            }
        }
        __syncthreads();
    }

    // epilogue: write split triple [hi|hi|lo] rows of g_o2 directly
    float inv0 = 1.0f / l0, inv1 = 1.0f / l1;
    int r0 = q0 + wid * 16 + (lane >> 2);
    int r1 = r0 + 8;
    __nv_bfloat16* row0 = g_o2 + (size_t)(b * Tc + r0) * KTOT;
    __nv_bfloat16* row1 = g_o2 + (size_t)(b * Tc + r1) * KTOT;
#pragma unroll
    for (int nf = 0; nf < 8; nf++) {
        int n = h * HDc + nf * 8 + 2 * (lane & 3);
        float v00 = o_acc[nf][0] * inv0, v01 = o_acc[nf][1] * inv0;
        float v10 = o_acc[nf][2] * inv1, v11 = o_acc[nf][3] * inv1;
        uint32_t hi0 = pkbf(v00, v01);
        uint32_t lo0 = pkbf(v00 - bfr(v00), v01 - bfr(v01));
        uint32_t hi1 = pkbf(v10, v11);
        uint32_t lo1 = pkbf(v10 - bfr(v10), v11 - bfr(v11));
        *(uint32_t*)(row0 + n)        = hi0;
        *(uint32_t*)(row0 + 1024 + n) = hi0;
        *(uint32_t*)(row0 + 2048 + n) = lo0;
        *(uint32_t*)(row1 + n)        = hi1;
        *(uint32_t*)(row1 + 1024 + n) = hi1;
        *(uint32_t*)(row1 + 2048 + n) = lo1;
    }
}

// ---------------------------------------------------------------------------
extern "C" void kernel_launch(void* const* d_in, const int* in_sizes, int n_in,
                              void* d_out, int out_size) {
    const float* x   = (const float*)d_in[0];
    const float* Wq  = (const float*)d_in[1];
    const float* bq  = (const float*)d_in[2];
    const float* Wk  = (const float*)d_in[3];
    const float* bk  = (const float*)d_in[4];
    const float* Wv  = (const float*)d_in[5];
    const float* bv  = (const float*)d_in[6];
    const float* Wo  = (const float*)d_in[7];
    const float* bo  = (const float*)d_in[8];
    const float* A   = (const float*)d_in[9];
    const float* ll  = (const float*)d_in[10];
    float* out = (float*)d_out;

    cudaFuncSetAttribute(gemm_tc, cudaFuncAttributeMaxDynamicSharedMemorySize, SMEM_DYN);
    cudaFuncSetAttribute(attn_tc, cudaFuncAttributeMaxDynamicSharedMemorySize, ASMEM);

    __nv_bfloat16 *x2, *w2qkv, *w2o, *o2;
    float* bqkv;
    cudaGetSymbolAddress((void**)&x2,    g_x2);
    cudaGetSymbolAddress((void**)&w2qkv, g_w2);
    cudaGetSymbolAddress((void**)&o2,    g_o2);
    cudaGetSymbolAddress((void**)&bqkv,  g_bqkv);
    w2o = w2qkv + (size_t)3 * Dc * KTOT;

    const float* Ws[4] = {Wq, Wk, Wv, Wo};

    split_kernel<<<(Mc*Dc/2 + 255)/256, 256>>>(x, x2, Mc, 0);
    for (int i = 0; i < 4; i++)
        split_kernel<<<(Dc*Dc/2 + 255)/256, 256>>>(Ws[i], w2qkv + (size_t)i*Dc*KTOT, Dc, 1);
    bias_concat<<<12, 256>>>(bq, bk, bv);

    // fused QKV: N = 3072, routing by n-tile
    gemm_tc<<<dim3(Mc/BM, 3*Dc/BN), 256, SMEM_DYN>>>(x2, w2qkv, bqkv, nullptr, 0);

    gdiag_kernel<<<4, 256>>>(A, ll);
    ksum2_kernel<<<Bc*Hc, 256>>>();
    sgprep_kernel<<<(Bc*Hc*Tc*HDc + 255)/256, 256>>>();

    attn_tc<<<dim3(Tc / AT_M, Bc * Hc), 256, ASMEM>>>();

    // final projection
    gemm_tc<<<dim3(Mc/BM, Dc/BN), 256, SMEM_DYN>>>(o2, w2o, bo, out, 1);
}

// round 6
// speedup vs baseline: 1.1204x; 1.1204x over previous
#include <cuda_runtime.h>
#include <cuda_bf16.h>
#include <cuda_fp16.h>
#include <math_constants.h>
#include <cstdint>

#define Bc 2
#define Tc 2048
#define Dc 1024
#define Hc 16
#define HDc 64
#define Mc (Bc*Tc)

#define KTOT 3072          // tripled K for split-bf16 3-product GEMM
#define BM 128
#define BN 256
#define BK 32
#define LDS_ROW 40
#define A_STG (BM*LDS_ROW*2)              // 10240
#define B_STG (BN*LDS_ROW*2)              // 20480
#define STG_BYTES (A_STG+B_STG)           // 30720
#define STAGES 4
#define SMEM_DYN (STAGES*STG_BYTES)       // 122880

// attention tiling
#define AT_M 128
#define LDSA 200
#define LDV  72
#define SG_BYTES_A (128*LDSA*2)           // 51200
#define K2STG (64*LDSA*2)                 // 25600
#define VTSTG (64*LDV*2)                  // 9216 (single fp16 plane)
#define ASMEM (SG_BYTES_A + 2*K2STG + 2*VTSTG)  // 120832

// ---------------- scratch (device globals; no runtime allocation) ----------
__device__ __align__(16) float g_q[Bc*Hc*Tc*HDc];      // (b,h,t,hd) fp32
__device__ __align__(16) float g_ksum[Bc*Hc*HDc];
__device__ __align__(16) float g_gdiag[Hc*HDc];
__device__ __align__(16) float g_bqkv[3*Dc];
__device__ __align__(16) __nv_bfloat16 g_x2[Mc*KTOT];        // [hi|hi|lo] of x
__device__ __align__(16) __nv_bfloat16 g_w2[3][Dc*KTOT];     // [hi|lo|hi] Wq,Wk,Wv
__device__ __align__(16) __half g_w2o[Dc*2048];              // [Whi|Whi] fp16 of Wo
__device__ __align__(16) __half g_o2[Mc*2048];               // [hi|lo] fp16 attn out
__device__ __align__(16) __nv_bfloat16 g_k2[Bc*Hc*Tc*192];   // [hi|lo|hi] key rows
__device__ __align__(16) __nv_bfloat16 g_sg2[Bc*Hc*Tc*192];  // [hi|hi|lo] Sg rows
__device__ __align__(16) __half g_v2t[Bc*Hc*HDc*Tc];         // [bh][d][t] fp16 V^T

// ---------------- PTX helpers ----------------------------------------------
__device__ __forceinline__ uint32_t smem_u32(const void* p) {
    uint32_t a;
    asm("{ .reg .u64 t; cvta.to.shared.u64 t, %1; cvt.u32.u64 %0, t; }" : "=r"(a) : "l"(p));
    return a;
}
#define CP_ASYNC16(sm, gm) \
    asm volatile("cp.async.cg.shared.global [%0], [%1], 16;" :: "r"(sm), "l"(gm))
#define CP_COMMIT() asm volatile("cp.async.commit_group;" ::: "memory")
#define CP_WAIT(n)  asm volatile("cp.async.wait_group %0;" :: "n"(n) : "memory")

__device__ __forceinline__ void ldsm_x4(uint32_t& r0, uint32_t& r1,
                                        uint32_t& r2, uint32_t& r3, uint32_t addr) {
    asm volatile("ldmatrix.sync.aligned.m8n8.x4.shared.b16 {%0,%1,%2,%3}, [%4];"
                 : "=r"(r0), "=r"(r1), "=r"(r2), "=r"(r3) : "r"(addr));
}
__device__ __forceinline__ void mma_bf(float* c, const uint32_t* a, const uint32_t* b) {
    asm volatile(
        "mma.sync.aligned.m16n8k16.row.col.f32.bf16.bf16.f32 "
        "{%0,%1,%2,%3}, {%4,%5,%6,%7}, {%8,%9}, {%0,%1,%2,%3};"
        : "+f"(c[0]), "+f"(c[1]), "+f"(c[2]), "+f"(c[3])
        : "r"(a[0]), "r"(a[1]), "r"(a[2]), "r"(a[3]), "r"(b[0]), "r"(b[1]));
}
__device__ __forceinline__ void mma_hf(float* c, const uint32_t* a, const uint32_t* b) {
    asm volatile(
        "mma.sync.aligned.m16n8k16.row.col.f32.f16.f16.f32 "
        "{%0,%1,%2,%3}, {%4,%5,%6,%7}, {%8,%9}, {%0,%1,%2,%3};"
        : "+f"(c[0]), "+f"(c[1]), "+f"(c[2]), "+f"(c[3])
        : "r"(a[0]), "r"(a[1]), "r"(a[2]), "r"(a[3]), "r"(b[0]), "r"(b[1]));
}
__device__ __forceinline__ uint32_t pkbf(float lo, float hi) {
    uint32_t r;
    asm("cvt.rn.bf16x2.f32 %0, %1, %2;" : "=r"(r) : "f"(hi), "f"(lo));
    return r;
}
__device__ __forceinline__ uint32_t pkhf(float lo, float hi) {
    uint32_t r;
    asm("cvt.rn.f16x2.f32 %0, %1, %2;" : "=r"(r) : "f"(hi), "f"(lo));
    return r;
}
__device__ __forceinline__ float bfr(float x) {
    return __bfloat162float(__float2bfloat16(x));
}
__device__ __forceinline__ float hfr(float x) {
    return __half2float(__float2half_rn(x));
}

// ---------------------------------------------------------------------------
// split fp32 -> bf16 triple. mode 0 (A): [hi|hi|lo]; mode 1 (B): [hi|lo|hi].
// ---------------------------------------------------------------------------
__global__ void split_kernel(const float* __restrict__ src,
                             __nv_bfloat16* __restrict__ dst, int rows, int mode) {
    int idx = blockIdx.x * blockDim.x + threadIdx.x;
    if (idx >= rows * (Dc/2)) return;
    float2 v = ((const float2*)src)[idx];
    int r = idx / (Dc/2), c2 = idx % (Dc/2);
    __nv_bfloat162 hi, lo;
    hi.x = __float2bfloat16(v.x); hi.y = __float2bfloat16(v.y);
    lo.x = __float2bfloat16(v.x - __bfloat162float(hi.x));
    lo.y = __float2bfloat16(v.y - __bfloat162float(hi.y));
    __nv_bfloat162* d = (__nv_bfloat162*)(dst + (size_t)r * KTOT);
    if (mode == 0) { d[c2] = hi; d[512 + c2] = hi; d[1024 + c2] = lo; }
    else           { d[c2] = hi; d[512 + c2] = lo; d[1024 + c2] = hi; }
}

// Wo -> fp16 [hi|hi] (K=2048); dropped term is o . (Wo - fp16(Wo)) ~ 1.3e-4
__global__ void wsplit_h(const float* __restrict__ W) {
    int idx = blockIdx.x * blockDim.x + threadIdx.x;
    if (idx >= Dc * Dc) return;
    int r = idx >> 10, c = idx & 1023;
    __half h = __float2half_rn(W[idx]);
    g_w2o[(size_t)r * 2048 + c] = h;
    g_w2o[(size_t)r * 2048 + 1024 + c] = h;
}

__global__ void bias_concat(const float* __restrict__ bq, const float* __restrict__ bk,
                            const float* __restrict__ bv) {
    int i = blockIdx.x * blockDim.x + threadIdx.x;
    if (i >= 3 * Dc) return;
    g_bqkv[i] = (i < Dc) ? bq[i] : (i < 2*Dc) ? bk[i - Dc] : bv[i - 2*Dc];
}

// ---------------------------------------------------------------------------
// mma.sync GEMM, tile 128x256, warp tile 64x64, BK=32, 4-stage cp.async.
// FP16M=0: bf16 mma (fused QKV, mode 0, routing by n0>>10);
// FP16M=1: fp16 mma (final projection, mode 1 -> Yext).
// ktot = K extent (and row stride) in elements.
// ---------------------------------------------------------------------------
template<int FP16M>
__global__ __launch_bounds__(256)
void gemm_tc(const void* __restrict__ A2, const void* __restrict__ W2,
             const float* __restrict__ bias, float* __restrict__ Yext,
             int mode, int ktot)
{
    extern __shared__ __align__(16) char dsmem[];
    uint32_t base = smem_u32(dsmem);

    int tid = threadIdx.x, wid = tid >> 5, lane = tid & 31;
    int wm = wid & 1, wn = wid >> 1;
    int m0 = blockIdx.x * BM, n0 = blockIdx.y * BN;

    const char* gA = (const char*)A2 + (size_t)m0 * ktot * 2;
    const char* gW = (const char*)W2 + (size_t)n0 * ktot * 2;
    size_t kstride = (size_t)ktot * 2;

    auto load_chunk = [&](int c) {
        uint32_t sa = base + (c % STAGES) * STG_BYTES;
        uint32_t sb = sa + A_STG;
        size_t k0 = (size_t)c * (BK * 2);
#pragma unroll
        for (int it = 0; it < 2; it++) {
            int ch = tid + it * 256;
            int r = ch >> 2, off = (ch & 3) * 16;
            CP_ASYNC16(sa + r * (LDS_ROW*2) + off, gA + r * kstride + k0 + off);
        }
#pragma unroll
        for (int it = 0; it < 4; it++) {
            int ch = tid + it * 256;
            int r = ch >> 2, off = (ch & 3) * 16;
            CP_ASYNC16(sb + r * (LDS_ROW*2) + off, gW + r * kstride + k0 + off);
        }
        CP_COMMIT();
    };

    float acc[4][8][4];
#pragma unroll
    for (int i = 0; i < 4; i++)
#pragma unroll
        for (int j = 0; j < 8; j++)
#pragma unroll
            for (int l = 0; l < 4; l++) acc[i][j][l] = 0.f;

    load_chunk(0);
    load_chunk(1);
    load_chunk(2);

    int a_row = wm * 64 + (lane & 15);
    int a_col8 = (lane >> 4) * 8;
    int b_row = wn * 64 + (lane & 7) + ((lane >> 4) << 3);
    int b_col8 = ((lane >> 3) & 1) * 8;
    int nk = ktot / BK;

#pragma unroll 1
    for (int i = 0; i < nk; i++) {
        CP_WAIT(STAGES - 2);
        __syncthreads();
        if (i + STAGES - 1 < nk) load_chunk(i + STAGES - 1);

        uint32_t sa = base + (i % STAGES) * STG_BYTES;
        uint32_t sb = sa + A_STG;
#pragma unroll
        for (int kk = 0; kk < 2; kk++) {
            uint32_t a[4][4], b[8][2];
#pragma unroll
            for (int mf = 0; mf < 4; mf++)
                ldsm_x4(a[mf][0], a[mf][1], a[mf][2], a[mf][3],
                        sa + ((a_row + mf*16) * LDS_ROW + kk*16 + a_col8) * 2);
#pragma unroll
            for (int np = 0; np < 4; np++)
                ldsm_x4(b[2*np][0], b[2*np][1], b[2*np+1][0], b[2*np+1][1],
                        sb + ((b_row + np*16) * LDS_ROW + kk*16 + b_col8) * 2);
#pragma unroll
            for (int mf = 0; mf < 4; mf++)
#pragma unroll
                for (int nf = 0; nf < 8; nf++) {
                    if (FP16M) mma_hf(acc[mf][nf], a[mf], b[nf]);
                    else       mma_bf(acc[mf][nf], a[mf], b[nf]);
                }
        }
    }

    int proj = n0 >> 10;                 // constant per CTA
#pragma unroll
    for (int mf = 0; mf < 4; mf++) {
#pragma unroll
        for (int nf = 0; nf < 8; nf++) {
            int m = m0 + wm*64 + mf*16 + (lane >> 2);
            int n = n0 + wn*64 + nf*8 + 2*(lane & 3);
            float b0 = bias[n], b1 = bias[n+1];
#pragma unroll
            for (int half = 0; half < 2; half++) {
                int mm = m + half * 8;
                float v0 = acc[mf][nf][half*2+0] + b0;
                float v1 = acc[mf][nf][half*2+1] + b1;
                int bb = mm >> 11, t = mm & 2047;
                int nn = n & 1023;
                int h = nn >> 6, d = nn & 63;
                int bh = bb * Hc + h;
                if (mode == 1) {
                    *(float2*)(Yext + (size_t)mm * Dc + n) = make_float2(v0, v1);
                } else if (proj == 0) {
                    *(float2*)(g_q + ((size_t)bh * Tc + t) * HDc + d) =
                        make_float2(v0, v1);
                } else if (proj == 1) {
                    __nv_bfloat16 h0 = __float2bfloat16(v0);
                    __nv_bfloat16 l0 = __float2bfloat16(v0 - __bfloat162float(h0));
                    __nv_bfloat16 h1 = __float2bfloat16(v1);
                    __nv_bfloat16 l1 = __float2bfloat16(v1 - __bfloat162float(h1));
                    __nv_bfloat16* row = g_k2 + ((size_t)bh * Tc + t) * 192;
                    row[d] = h0;   row[d+1] = h1;
                    row[64+d] = l0; row[64+d+1] = l1;
                    row[128+d] = h0; row[128+d+1] = h1;
                } else {
                    __half* pbase = g_v2t + (size_t)bh * HDc * Tc;
                    pbase[(size_t)d * Tc + t]     = __float2half_rn(v0);
                    pbase[(size_t)(d+1) * Tc + t] = __float2half_rn(v1);
                }
            }
        }
    }
}

// ---------------------------------------------------------------------------
__global__ void gdiag_kernel(const float* __restrict__ A,
                             const float* __restrict__ log_lambda) {
    int i = blockIdx.x * blockDim.x + threadIdx.x;
    if (i >= Hc * HDc) return;
    int h = i >> 6, d = i & 63;
    float s = expf(log_lambda[h]);
#pragma unroll
    for (int r = 0; r < 16; r++) {
        float a = A[(h * 16 + r) * HDc + d];
        s = fmaf(a, a, s);
    }
    g_gdiag[i] = s;
}

__global__ __launch_bounds__(256) void ksum2_kernel() {
    __shared__ float red[256];
    int bh = blockIdx.x;
    int d = threadIdx.x & 63, chunk = threadIdx.x >> 6;
    const __nv_bfloat16* base = g_k2 + (size_t)bh * Tc * 192;
    float s = 0.f;
    for (int t = chunk * 512; t < (chunk + 1) * 512; t++) {
        const __nv_bfloat16* row = base + (size_t)t * 192;
        s += __bfloat162float(row[d]) + __bfloat162float(row[64 + d]);
    }
    red[threadIdx.x] = s;
    __syncthreads();
    if (chunk == 0) {
        float tot = red[d] + red[64+d] + red[128+d] + red[192+d];
        g_ksum[bh * HDc + d] = tot;
    }
}

__global__ void sgprep_kernel() {
    int idx = blockIdx.x * blockDim.x + threadIdx.x;
    if (idx >= Bc*Hc*Tc*HDc) return;
    int bh = idx >> 17;
    int rem = idx & 131071;
    int t = rem >> 6, d = rem & 63;
    float q = g_q[((size_t)bh * Tc + t) * HDc + d];
    float sg = (2048.0f * q - g_ksum[bh * HDc + d]) * g_gdiag[(bh & 15) * HDc + d];
    __nv_bfloat16 hi = __float2bfloat16(sg);
    __nv_bfloat16 lo = __float2bfloat16(sg - __bfloat162float(hi));
    __nv_bfloat16* row = g_sg2 + ((size_t)bh * Tc + t) * 192;
    row[d] = hi; row[64 + d] = hi; row[128 + d] = lo;
}

// ---------------------------------------------------------------------------
// Tensor-core flash attention. QK: bf16 3-product (K=192). PV: fp16 2-chain
// (Phi+Plo) x Vhi. Epilogue writes fp16 [hi|lo] rows of g_o2 (K=2048).
// ---------------------------------------------------------------------------
__global__ __launch_bounds__(256, 1)
void attn_tc() {
    extern __shared__ __align__(16) char asmem[];
    uint32_t sgs = smem_u32(asmem);
    uint32_t k2s = sgs + SG_BYTES_A;
    uint32_t vts = k2s + 2 * K2STG;

    int tid = threadIdx.x, wid = tid >> 5, lane = tid & 31;
    int bh = blockIdx.y, h = bh & 15, b = bh >> 4;
    int q0 = blockIdx.x * AT_M;

    const __nv_bfloat16* sg_g = g_sg2 + ((size_t)bh * Tc + q0) * 192;
    const __nv_bfloat16* k_g  = g_k2  + (size_t)bh * Tc * 192;
    const __half*        v_g  = g_v2t + (size_t)bh * HDc * Tc;

#pragma unroll
    for (int it = 0; it < 12; it++) {
        int id = tid + it * 256;
        int r = id / 24, c = id % 24;
        CP_ASYNC16(sgs + r * (LDSA*2) + c * 16, (const char*)(sg_g + (size_t)r * 192 + c * 8));
    }
    CP_COMMIT();

    auto load_tile = [&](int ti) {
        int st = ti & 1;
        int j0 = ti * 64;
        uint32_t kd = k2s + st * K2STG;
        uint32_t vd = vts + st * VTSTG;
#pragma unroll
        for (int it = 0; it < 6; it++) {          // K: 64 x 192 bf16
            int id = tid + it * 256;
            int r = id / 24, c = id % 24;
            CP_ASYNC16(kd + r * (LDSA*2) + c * 16,
                       (const char*)(k_g + (size_t)(j0 + r) * 192 + c * 8));
        }
#pragma unroll
        for (int it = 0; it < 2; it++) {          // V^T: 64 x 64 fp16
            int id = tid + it * 256;
            int r = id >> 3, c = id & 7;
            CP_ASYNC16(vd + r * (LDV*2) + c * 16,
                       (const char*)(v_g + (size_t)r * Tc + j0 + c * 8));
        }
        CP_COMMIT();
    };

    load_tile(0);
    CP_WAIT(1);
    __syncthreads();

    uint32_t aq[12][4];
    {
        int arow = wid * 16 + (lane & 15);
        int acol = (lane >> 4) * 8;
#pragma unroll
        for (int kc = 0; kc < 12; kc++)
            ldsm_x4(aq[kc][0], aq[kc][1], aq[kc][2], aq[kc][3],
                    sgs + (arow * LDSA + kc * 16 + acol) * 2);
    }

    float o_acc[8][4];
#pragma unroll
    for (int nf = 0; nf < 8; nf++)
#pragma unroll
        for (int l = 0; l < 4; l++) o_acc[nf][l] = 0.f;
    float m0 = -CUDART_INF_F, m1 = -CUDART_INF_F, l0 = 0.f, l1 = 0.f;

    int brow = (lane & 7) + ((lane >> 4) << 3);
    int bcol8 = ((lane >> 3) & 1) * 8;

#pragma unroll 1
    for (int ti = 0; ti < 32; ti++) {
        if (ti + 1 < 32) { load_tile(ti + 1); CP_WAIT(1); }
        else CP_WAIT(0);
        __syncthreads();
        int st = ti & 1;
        uint32_t kd = k2s + st * K2STG;
        uint32_t vd = vts + st * VTSTG;

        float s[8][4];
#pragma unroll
        for (int nf = 0; nf < 8; nf++)
#pragma unroll
            for (int l = 0; l < 4; l++) s[nf][l] = 0.f;
#pragma unroll
        for (int kc = 0; kc < 12; kc++) {
            uint32_t bq[8][2];
#pragma unroll
            for (int np = 0; np < 4; np++)
                ldsm_x4(bq[2*np][0], bq[2*np][1], bq[2*np+1][0], bq[2*np+1][1],
                        kd + ((np*16 + brow) * LDSA + kc*16 + bcol8) * 2);
#pragma unroll
            for (int nf = 0; nf < 8; nf++)
                mma_bf(s[nf], aq[kc], bq[nf]);
        }

        float rm0 = -CUDART_INF_F, rm1 = -CUDART_INF_F;
#pragma unroll
        for (int nf = 0; nf < 8; nf++) {
            rm0 = fmaxf(rm0, fmaxf(s[nf][0], s[nf][1]));
            rm1 = fmaxf(rm1, fmaxf(s[nf][2], s[nf][3]));
        }
        rm0 = fmaxf(rm0, __shfl_xor_sync(0xffffffffu, rm0, 1));
        rm0 = fmaxf(rm0, __shfl_xor_sync(0xffffffffu, rm0, 2));
        rm1 = fmaxf(rm1, __shfl_xor_sync(0xffffffffu, rm1, 1));
        rm1 = fmaxf(rm1, __shfl_xor_sync(0xffffffffu, rm1, 2));
        float mn0 = fmaxf(m0, rm0), mn1 = fmaxf(m1, rm1);
        float sc0 = __expf(m0 - mn0), sc1 = __expf(m1 - mn1);
        m0 = mn0; m1 = mn1;
        float rs0 = 0.f, rs1 = 0.f;
#pragma unroll
        for (int nf = 0; nf < 8; nf++) {
            s[nf][0] = __expf(s[nf][0] - mn0);
            s[nf][1] = __expf(s[nf][1] - mn0);
            s[nf][2] = __expf(s[nf][2] - mn1);
            s[nf][3] = __expf(s[nf][3] - mn1);
            rs0 += s[nf][0] + s[nf][1];
            rs1 += s[nf][2] + s[nf][3];
        }
        rs0 += __shfl_xor_sync(0xffffffffu, rs0, 1);
        rs0 += __shfl_xor_sync(0xffffffffu, rs0, 2);
        rs1 += __shfl_xor_sync(0xffffffffu, rs1, 1);
        rs1 += __shfl_xor_sync(0xffffffffu, rs1, 2);
        l0 = l0 * sc0 + rs0;
        l1 = l1 * sc1 + rs1;
#pragma unroll
        for (int nf = 0; nf < 8; nf++) {
            o_acc[nf][0] *= sc0; o_acc[nf][1] *= sc0;
            o_acc[nf][2] *= sc1; o_acc[nf][3] *= sc1;
        }

        // P -> fp16 hi/lo A-fragments (4 k16 chunks)
        uint32_t Ahi[4][4], Alo[4][4];
#pragma unroll
        for (int kc = 0; kc < 4; kc++) {
            int f0 = 2*kc, f1 = 2*kc + 1;
            float h00 = hfr(s[f0][0]), h01 = hfr(s[f0][1]);
            float h02 = hfr(s[f0][2]), h03 = hfr(s[f0][3]);
            float h10 = hfr(s[f1][0]), h11 = hfr(s[f1][1]);
            float h12 = hfr(s[f1][2]), h13 = hfr(s[f1][3]);
            Ahi[kc][0] = pkhf(h00, h01);
            Ahi[kc][1] = pkhf(h02, h03);
            Ahi[kc][2] = pkhf(h10, h11);
            Ahi[kc][3] = pkhf(h12, h13);
            Alo[kc][0] = pkhf(s[f0][0]-h00, s[f0][1]-h01);
            Alo[kc][1] = pkhf(s[f0][2]-h02, s[f0][3]-h03);
            Alo[kc][2] = pkhf(s[f1][0]-h10, s[f1][1]-h11);
            Alo[kc][3] = pkhf(s[f1][2]-h12, s[f1][3]-h13);
        }

        // PV: o += Phi*Vh + Plo*Vh  (fp16, 2 chains)
#pragma unroll
        for (int kc = 0; kc < 4; kc++) {
            uint32_t bvh[8][2];
#pragma unroll
            for (int np = 0; np < 4; np++)
                ldsm_x4(bvh[2*np][0], bvh[2*np][1], bvh[2*np+1][0], bvh[2*np+1][1],
                        vd + ((np*16 + brow) * LDV + kc*16 + bcol8) * 2);
#pragma unroll
            for (int nf = 0; nf < 8; nf++) {
                mma_hf(o_acc[nf], Ahi[kc], bvh[nf]);
                mma_hf(o_acc[nf], Alo[kc], bvh[nf]);
            }
        }
        __syncthreads();
    }

    // epilogue: write fp16 [hi|lo] rows of g_o2 (K = 2048)
    float inv0 = 1.0f / l0, inv1 = 1.0f / l1;
    int r0 = q0 + wid * 16 + (lane >> 2);
    int r1 = r0 + 8;
    __half* row0 = g_o2 + (size_t)(b * Tc + r0) * 2048;
    __half* row1 = g_o2 + (size_t)(b * Tc + r1) * 2048;
#pragma unroll
    for (int nf = 0; nf < 8; nf++) {
        int n = h * HDc + nf * 8 + 2 * (lane & 3);
        float v00 = o_acc[nf][0] * inv0, v01 = o_acc[nf][1] * inv0;
        float v10 = o_acc[nf][2] * inv1, v11 = o_acc[nf][3] * inv1;
        float e00 = hfr(v00), e01 = hfr(v01), e10 = hfr(v10), e11 = hfr(v11);
        *(uint32_t*)(row0 + n)        = pkhf(e00, e01);
        *(uint32_t*)(row0 + 1024 + n) = pkhf(v00 - e00, v01 - e01);
        *(uint32_t*)(row1 + n)        = pkhf(e10, e11);
        *(uint32_t*)(row1 + 1024 + n) = pkhf(v10 - e10, v11 - e11);
    }
}

// ---------------------------------------------------------------------------
extern "C" void kernel_launch(void* const* d_in, const int* in_sizes, int n_in,
                              void* d_out, int out_size) {
    const float* x   = (const float*)d_in[0];
    const float* Wq  = (const float*)d_in[1];
    const float* bq  = (const float*)d_in[2];
    const float* Wk  = (const float*)d_in[3];
    const float* bk  = (const float*)d_in[4];
    const float* Wv  = (const float*)d_in[5];
    const float* bv  = (const float*)d_in[6];
    const float* Wo  = (const float*)d_in[7];
    const float* bo  = (const float*)d_in[8];
    const float* A   = (const float*)d_in[9];
    const float* ll  = (const float*)d_in[10];
    float* out = (float*)d_out;

    cudaFuncSetAttribute(gemm_tc<0>, cudaFuncAttributeMaxDynamicSharedMemorySize, SMEM_DYN);
    cudaFuncSetAttribute(gemm_tc<1>, cudaFuncAttributeMaxDynamicSharedMemorySize, SMEM_DYN);
    cudaFuncSetAttribute(attn_tc, cudaFuncAttributeMaxDynamicSharedMemorySize, ASMEM);

    void *x2, *w2qkv, *w2oh, *o2h;
    float* bqkv;
    cudaGetSymbolAddress(&x2,    g_x2);
    cudaGetSymbolAddress(&w2qkv, g_w2);
    cudaGetSymbolAddress(&w2oh,  g_w2o);
    cudaGetSymbolAddress(&o2h,   g_o2);
    cudaGetSymbolAddress((void**)&bqkv, g_bqkv);

    const float* Ws[3] = {Wq, Wk, Wv};

    split_kernel<<<(Mc*Dc/2 + 255)/256, 256>>>(x, (__nv_bfloat16*)x2, Mc, 0);
    for (int i = 0; i < 3; i++)
        split_kernel<<<(Dc*Dc/2 + 255)/256, 256>>>(
            Ws[i], (__nv_bfloat16*)w2qkv + (size_t)i*Dc*KTOT, Dc, 1);
    wsplit_h<<<(Dc*Dc + 255)/256, 256>>>(Wo);
    bias_concat<<<12, 256>>>(bq, bk, bv);

    // fused QKV: N = 3072, bf16 3-product, K=3072
    gemm_tc<0><<<dim3(Mc/BM, 3*Dc/BN), 256, SMEM_DYN>>>(x2, w2qkv, bqkv, nullptr, 0, KTOT);

    gdiag_kernel<<<4, 256>>>(A, ll);
    ksum2_kernel<<<Bc*Hc, 256>>>();
    sgprep_kernel<<<(Bc*Hc*Tc*HDc + 255)/256, 256>>>();

    attn_tc<<<dim3(Tc / AT_M, Bc * Hc), 256, ASMEM>>>();

    // final projection: fp16 2-product, K=2048
    gemm_tc<1><<<dim3(Mc/BM, Dc/BN), 256, SMEM_DYN>>>(o2h, w2oh, bo, out, 1, 2048);
}

// round 7
// speedup vs baseline: 1.2332x; 1.1007x over previous
#include <cuda_runtime.h>
#include <cuda_bf16.h>
#include <cuda_fp16.h>
#include <math_constants.h>
#include <cstdint>

#define Bc 2
#define Tc 2048
#define Dc 1024
#define Hc 16
#define HDc 64
#define Mc (Bc*Tc)

#define KTOT 3072          // tripled K for split-bf16 3-product GEMM
#define BM 128
#define BN 256
#define BK 32
#define LDS_ROW 40
#define A_STG (BM*LDS_ROW*2)              // 10240
#define B_STG (BN*LDS_ROW*2)              // 20480
#define STG_BYTES (A_STG+B_STG)           // 30720
#define STAGES 4
#define SMEM_DYN (STAGES*STG_BYTES)       // 122880

// attention tiling
#define AT_M 128
#define LDSA 200
#define LDV  72
#define SG_BYTES_A (128*LDSA*2)           // 51200
#define K2STG (64*LDSA*2)                 // 25600
#define VTSTG (64*LDV*2)                  // 9216 (single fp16 plane)
#define ASMEM (SG_BYTES_A + 2*K2STG + 2*VTSTG)  // 120832

// ---------------- scratch (device globals; no runtime allocation) ----------
__device__ __align__(16) float g_q[Bc*Hc*Tc*HDc];      // (b,h,t,hd) fp32
__device__ __align__(16) float g_ksum[Bc*Hc*HDc];
__device__ __align__(16) float g_gdiag[Hc*HDc];
__device__ __align__(16) float g_bqk[2*Dc];
__device__ __align__(16) __nv_bfloat16 g_x2[Mc*KTOT];        // [hi|hi|lo] of x (bf16)
__device__ __align__(16) __half g_x2h[Mc*2048];              // [hi|lo] of x (fp16)
__device__ __align__(16) __nv_bfloat16 g_w2[2][Dc*KTOT];     // [hi|lo|hi] Wq,Wk
__device__ __align__(16) __half g_w2v[Dc*2048];              // [hi|hi] fp16 of Wv
__device__ __align__(16) __half g_w2o[Dc*2048];              // [hi|hi] fp16 of Wo
__device__ __align__(16) __half g_o2[Mc*2048];               // [hi|lo] fp16 attn out
__device__ __align__(16) __nv_bfloat16 g_k2[Bc*Hc*Tc*192];   // [hi|lo|hi] key rows
__device__ __align__(16) __nv_bfloat16 g_sg2[Bc*Hc*Tc*192];  // [hi|hi|lo] Sg rows
__device__ __align__(16) __half g_v2t[Bc*Hc*HDc*Tc];         // [bh][d][t] fp16 V^T

// ---------------- PTX helpers ----------------------------------------------
__device__ __forceinline__ uint32_t smem_u32(const void* p) {
    uint32_t a;
    asm("{ .reg .u64 t; cvta.to.shared.u64 t, %1; cvt.u32.u64 %0, t; }" : "=r"(a) : "l"(p));
    return a;
}
#define CP_ASYNC16(sm, gm) \
    asm volatile("cp.async.cg.shared.global [%0], [%1], 16;" :: "r"(sm), "l"(gm))
#define CP_COMMIT() asm volatile("cp.async.commit_group;" ::: "memory")
#define CP_WAIT(n)  asm volatile("cp.async.wait_group %0;" :: "n"(n) : "memory")

__device__ __forceinline__ void ldsm_x4(uint32_t& r0, uint32_t& r1,
                                        uint32_t& r2, uint32_t& r3, uint32_t addr) {
    asm volatile("ldmatrix.sync.aligned.m8n8.x4.shared.b16 {%0,%1,%2,%3}, [%4];"
                 : "=r"(r0), "=r"(r1), "=r"(r2), "=r"(r3) : "r"(addr));
}
__device__ __forceinline__ void mma_bf(float* c, const uint32_t* a, const uint32_t* b) {
    asm volatile(
        "mma.sync.aligned.m16n8k16.row.col.f32.bf16.bf16.f32 "
        "{%0,%1,%2,%3}, {%4,%5,%6,%7}, {%8,%9}, {%0,%1,%2,%3};"
        : "+f"(c[0]), "+f"(c[1]), "+f"(c[2]), "+f"(c[3])
        : "r"(a[0]), "r"(a[1]), "r"(a[2]), "r"(a[3]), "r"(b[0]), "r"(b[1]));
}
__device__ __forceinline__ void mma_hf(float* c, const uint32_t* a, const uint32_t* b) {
    asm volatile(
        "mma.sync.aligned.m16n8k16.row.col.f32.f16.f16.f32 "
        "{%0,%1,%2,%3}, {%4,%5,%6,%7}, {%8,%9}, {%0,%1,%2,%3};"
        : "+f"(c[0]), "+f"(c[1]), "+f"(c[2]), "+f"(c[3])
        : "r"(a[0]), "r"(a[1]), "r"(a[2]), "r"(a[3]), "r"(b[0]), "r"(b[1]));
}
__device__ __forceinline__ uint32_t pkhf(float lo, float hi) {
    uint32_t r;
    asm("cvt.rn.f16x2.f32 %0, %1, %2;" : "=r"(r) : "f"(hi), "f"(lo));
    return r;
}
__device__ __forceinline__ float hfr(float x) {
    return __half2float(__float2half_rn(x));
}

// ---------------------------------------------------------------------------
// split fp32 -> bf16 triple. mode 0 (A): [hi|hi|lo]; mode 1 (B): [hi|lo|hi].
// ---------------------------------------------------------------------------
__global__ void split_kernel(const float* __restrict__ src,
                             __nv_bfloat16* __restrict__ dst, int rows, int mode) {
    int idx = blockIdx.x * blockDim.x + threadIdx.x;
    if (idx >= rows * (Dc/2)) return;
    float2 v = ((const float2*)src)[idx];
    int r = idx / (Dc/2), c2 = idx % (Dc/2);
    __nv_bfloat162 hi, lo;
    hi.x = __float2bfloat16(v.x); hi.y = __float2bfloat16(v.y);
    lo.x = __float2bfloat16(v.x - __bfloat162float(hi.x));
    lo.y = __float2bfloat16(v.y - __bfloat162float(hi.y));
    __nv_bfloat162* d = (__nv_bfloat162*)(dst + (size_t)r * KTOT);
    if (mode == 0) { d[c2] = hi; d[512 + c2] = hi; d[1024 + c2] = lo; }
    else           { d[c2] = hi; d[512 + c2] = lo; d[1024 + c2] = hi; }
}

// x -> fp16 [hi|lo] A-format (K=2048)
__global__ void split_xh(const float* __restrict__ src) {
    int idx = blockIdx.x * blockDim.x + threadIdx.x;
    if (idx >= Mc * (Dc/2)) return;
    float2 v = ((const float2*)src)[idx];
    int r = idx / (Dc/2), c2 = idx % (Dc/2);
    __half2 hi, lo;
    hi.x = __float2half_rn(v.x); hi.y = __float2half_rn(v.y);
    lo.x = __float2half_rn(v.x - __half2float(hi.x));
    lo.y = __float2half_rn(v.y - __half2float(hi.y));
    __half2* d = (__half2*)(g_x2h + (size_t)r * 2048);
    d[c2] = hi; d[512 + c2] = lo;
}

// W -> fp16 [hi|hi] B-format (K=2048); dropped: x . (W - fp16(W)) ~ 2.4e-4
__global__ void wsplit_h(const float* __restrict__ W, __half* __restrict__ dst) {
    int idx = blockIdx.x * blockDim.x + threadIdx.x;
    if (idx >= Dc * Dc) return;
    int r = idx >> 10, c = idx & 1023;
    __half h = __float2half_rn(W[idx]);
    dst[(size_t)r * 2048 + c] = h;
    dst[(size_t)r * 2048 + 1024 + c] = h;
}

__global__ void bias_concat(const float* __restrict__ bq, const float* __restrict__ bk) {
    int i = blockIdx.x * blockDim.x + threadIdx.x;
    if (i >= 2 * Dc) return;
    g_bqk[i] = (i < Dc) ? bq[i] : bk[i - Dc];
}

// ---------------------------------------------------------------------------
// mma.sync GEMM, tile 128x256, warp tile 64x64, BK=32, 4-stage cp.async.
// FP16M=0: bf16 mma; FP16M=1: fp16 mma.
// mode 0: fused QK over N=2048 (n0>>10: q fp32 / k triple)
// mode 1: final projection -> Yext
// mode 2: V projection -> g_v2t fp16 plane
// ---------------------------------------------------------------------------
template<int FP16M>
__global__ __launch_bounds__(256)
void gemm_tc(const void* __restrict__ A2, const void* __restrict__ W2,
             const float* __restrict__ bias, float* __restrict__ Yext,
             int mode, int ktot)
{
    extern __shared__ __align__(16) char dsmem[];
    uint32_t base = smem_u32(dsmem);

    int tid = threadIdx.x, wid = tid >> 5, lane = tid & 31;
    int wm = wid & 1, wn = wid >> 1;
    int m0 = blockIdx.x * BM, n0 = blockIdx.y * BN;

    const char* gA = (const char*)A2 + (size_t)m0 * ktot * 2;
    const char* gW = (const char*)W2 + (size_t)n0 * ktot * 2;
    size_t kstride = (size_t)ktot * 2;

    auto load_chunk = [&](int c) {
        uint32_t sa = base + (c % STAGES) * STG_BYTES;
        uint32_t sb = sa + A_STG;
        size_t k0 = (size_t)c * (BK * 2);
#pragma unroll
        for (int it = 0; it < 2; it++) {
            int ch = tid + it * 256;
            int r = ch >> 2, off = (ch & 3) * 16;
            CP_ASYNC16(sa + r * (LDS_ROW*2) + off, gA + r * kstride + k0 + off);
        }
#pragma unroll
        for (int it = 0; it < 4; it++) {
            int ch = tid + it * 256;
            int r = ch >> 2, off = (ch & 3) * 16;
            CP_ASYNC16(sb + r * (LDS_ROW*2) + off, gW + r * kstride + k0 + off);
        }
        CP_COMMIT();
    };

    float acc[4][8][4];
#pragma unroll
    for (int i = 0; i < 4; i++)
#pragma unroll
        for (int j = 0; j < 8; j++)
#pragma unroll
            for (int l = 0; l < 4; l++) acc[i][j][l] = 0.f;

    load_chunk(0);
    load_chunk(1);
    load_chunk(2);

    int a_row = wm * 64 + (lane & 15);
    int a_col8 = (lane >> 4) * 8;
    int b_row = wn * 64 + (lane & 7) + ((lane >> 4) << 3);
    int b_col8 = ((lane >> 3) & 1) * 8;
    int nk = ktot / BK;

#pragma unroll 1
    for (int i = 0; i < nk; i++) {
        CP_WAIT(STAGES - 2);
        __syncthreads();
        if (i + STAGES - 1 < nk) load_chunk(i + STAGES - 1);

        uint32_t sa = base + (i % STAGES) * STG_BYTES;
        uint32_t sb = sa + A_STG;
#pragma unroll
        for (int kk = 0; kk < 2; kk++) {
            uint32_t a[4][4], b[8][2];
#pragma unroll
            for (int mf = 0; mf < 4; mf++)
                ldsm_x4(a[mf][0], a[mf][1], a[mf][2], a[mf][3],
                        sa + ((a_row + mf*16) * LDS_ROW + kk*16 + a_col8) * 2);
#pragma unroll
            for (int np = 0; np < 4; np++)
                ldsm_x4(b[2*np][0], b[2*np][1], b[2*np+1][0], b[2*np+1][1],
                        sb + ((b_row + np*16) * LDS_ROW + kk*16 + b_col8) * 2);
#pragma unroll
            for (int mf = 0; mf < 4; mf++)
#pragma unroll
                for (int nf = 0; nf < 8; nf++) {
                    if (FP16M) mma_hf(acc[mf][nf], a[mf], b[nf]);
                    else       mma_bf(acc[mf][nf], a[mf], b[nf]);
                }
        }
    }

    int proj = n0 >> 10;                 // constant per CTA (mode 0)
#pragma unroll
    for (int mf = 0; mf < 4; mf++) {
#pragma unroll
        for (int nf = 0; nf < 8; nf++) {
            int m = m0 + wm*64 + mf*16 + (lane >> 2);
            int n = n0 + wn*64 + nf*8 + 2*(lane & 3);
            float b0 = bias[n], b1 = bias[n+1];
#pragma unroll
            for (int half = 0; half < 2; half++) {
                int mm = m + half * 8;
                float v0 = acc[mf][nf][half*2+0] + b0;
                float v1 = acc[mf][nf][half*2+1] + b1;
                int bb = mm >> 11, t = mm & 2047;
                int nn = n & 1023;
                int h = nn >> 6, d = nn & 63;
                int bh = bb * Hc + h;
                if (mode == 1) {
                    *(float2*)(Yext + (size_t)mm * Dc + n) = make_float2(v0, v1);
                } else if (mode == 2) {
                    __half* pbase = g_v2t + (size_t)bh * HDc * Tc;
                    pbase[(size_t)d * Tc + t]     = __float2half_rn(v0);
                    pbase[(size_t)(d+1) * Tc + t] = __float2half_rn(v1);
                } else if (proj == 0) {
                    *(float2*)(g_q + ((size_t)bh * Tc + t) * HDc + d) =
                        make_float2(v0, v1);
                } else {
                    __nv_bfloat16 h0 = __float2bfloat16(v0);
                    __nv_bfloat16 l0 = __float2bfloat16(v0 - __bfloat162float(h0));
                    __nv_bfloat16 h1 = __float2bfloat16(v1);
                    __nv_bfloat16 l1 = __float2bfloat16(v1 - __bfloat162float(h1));
                    __nv_bfloat16* row = g_k2 + ((size_t)bh * Tc + t) * 192;
                    row[d] = h0;   row[d+1] = h1;
                    row[64+d] = l0; row[64+d+1] = l1;
                    row[128+d] = h0; row[128+d+1] = h1;
                }
            }
        }
    }
}

// ---------------------------------------------------------------------------
__global__ void gdiag_kernel(const float* __restrict__ A,
                             const float* __restrict__ log_lambda) {
    int i = blockIdx.x * blockDim.x + threadIdx.x;
    if (i >= Hc * HDc) return;
    int h = i >> 6, d = i & 63;
    float s = expf(log_lambda[h]);
#pragma unroll
    for (int r = 0; r < 16; r++) {
        float a = A[(h * 16 + r) * HDc + d];
        s = fmaf(a, a, s);
    }
    g_gdiag[i] = s;
}

__global__ __launch_bounds__(256) void ksum2_kernel() {
    __shared__ float red[256];
    int bh = blockIdx.x;
    int d = threadIdx.x & 63, chunk = threadIdx.x >> 6;
    const __nv_bfloat16* base = g_k2 + (size_t)bh * Tc * 192;
    float s = 0.f;
    for (int t = chunk * 512; t < (chunk + 1) * 512; t++) {
        const __nv_bfloat16* row = base + (size_t)t * 192;
        s += __bfloat162float(row[d]) + __bfloat162float(row[64 + d]);
    }
    red[threadIdx.x] = s;
    __syncthreads();
    if (chunk == 0) {
        float tot = red[d] + red[64+d] + red[128+d] + red[192+d];
        g_ksum[bh * HDc + d] = tot;
    }
}

__global__ void sgprep_kernel() {
    int idx = blockIdx.x * blockDim.x + threadIdx.x;
    if (idx >= Bc*Hc*Tc*HDc) return;
    int bh = idx >> 17;
    int rem = idx & 131071;
    int t = rem >> 6, d = rem & 63;
    float q = g_q[((size_t)bh * Tc + t) * HDc + d];
    float sg = (2048.0f * q - g_ksum[bh * HDc + d]) * g_gdiag[(bh & 15) * HDc + d];
    __nv_bfloat16 hi = __float2bfloat16(sg);
    __nv_bfloat16 lo = __float2bfloat16(sg - __bfloat162float(hi));
    __nv_bfloat16* row = g_sg2 + ((size_t)bh * Tc + t) * 192;
    row[d] = hi; row[64 + d] = hi; row[128 + d] = lo;
}

// ---------------------------------------------------------------------------
// Tensor-core flash attention. QK: bf16 3-product (K=192). PV: fp16 single
// chain Phi x Vhi. Epilogue writes fp16 [hi|lo] rows of g_o2 (K=2048).
// ---------------------------------------------------------------------------
__global__ __launch_bounds__(256, 1)
void attn_tc() {
    extern __shared__ __align__(16) char asmem[];
    uint32_t sgs = smem_u32(asmem);
    uint32_t k2s = sgs + SG_BYTES_A;
    uint32_t vts = k2s + 2 * K2STG;

    int tid = threadIdx.x, wid = tid >> 5, lane = tid & 31;
    int bh = blockIdx.y, h = bh & 15, b = bh >> 4;
    int q0 = blockIdx.x * AT_M;

    const __nv_bfloat16* sg_g = g_sg2 + ((size_t)bh * Tc + q0) * 192;
    const __nv_bfloat16* k_g  = g_k2  + (size_t)bh * Tc * 192;
    const __half*        v_g  = g_v2t + (size_t)bh * HDc * Tc;

#pragma unroll
    for (int it = 0; it < 12; it++) {
        int id = tid + it * 256;
        int r = id / 24, c = id % 24;
        CP_ASYNC16(sgs + r * (LDSA*2) + c * 16, (const char*)(sg_g + (size_t)r * 192 + c * 8));
    }
    CP_COMMIT();

    auto load_tile = [&](int ti) {
        int st = ti & 1;
        int j0 = ti * 64;
        uint32_t kd = k2s + st * K2STG;
        uint32_t vd = vts + st * VTSTG;
#pragma unroll
        for (int it = 0; it < 6; it++) {          // K: 64 x 192 bf16
            int id = tid + it * 256;
            int r = id / 24, c = id % 24;
            CP_ASYNC16(kd + r * (LDSA*2) + c * 16,
                       (const char*)(k_g + (size_t)(j0 + r) * 192 + c * 8));
        }
#pragma unroll
        for (int it = 0; it < 2; it++) {          // V^T: 64 x 64 fp16
            int id = tid + it * 256;
            int r = id >> 3, c = id & 7;
            CP_ASYNC16(vd + r * (LDV*2) + c * 16,
                       (const char*)(v_g + (size_t)r * Tc + j0 + c * 8));
        }
        CP_COMMIT();
    };

    load_tile(0);
    CP_WAIT(1);
    __syncthreads();

    uint32_t aq[12][4];
    {
        int arow = wid * 16 + (lane & 15);
        int acol = (lane >> 4) * 8;
#pragma unroll
        for (int kc = 0; kc < 12; kc++)
            ldsm_x4(aq[kc][0], aq[kc][1], aq[kc][2], aq[kc][3],
                    sgs + (arow * LDSA + kc * 16 + acol) * 2);
    }

    float o_acc[8][4];
#pragma unroll
    for (int nf = 0; nf < 8; nf++)
#pragma unroll
        for (int l = 0; l < 4; l++) o_acc[nf][l] = 0.f;
    float m0 = -CUDART_INF_F, m1 = -CUDART_INF_F, l0 = 0.f, l1 = 0.f;

    int brow = (lane & 7) + ((lane >> 4) << 3);
    int bcol8 = ((lane >> 3) & 1) * 8;

#pragma unroll 1
    for (int ti = 0; ti < 32; ti++) {
        if (ti + 1 < 32) { load_tile(ti + 1); CP_WAIT(1); }
        else CP_WAIT(0);
        __syncthreads();
        int st = ti & 1;
        uint32_t kd = k2s + st * K2STG;
        uint32_t vd = vts + st * VTSTG;

        float s[8][4];
#pragma unroll
        for (int nf = 0; nf < 8; nf++)
#pragma unroll
            for (int l = 0; l < 4; l++) s[nf][l] = 0.f;
#pragma unroll
        for (int kc = 0; kc < 12; kc++) {
            uint32_t bq[8][2];
#pragma unroll
            for (int np = 0; np < 4; np++)
                ldsm_x4(bq[2*np][0], bq[2*np][1], bq[2*np+1][0], bq[2*np+1][1],
                        kd + ((np*16 + brow) * LDSA + kc*16 + bcol8) * 2);
#pragma unroll
            for (int nf = 0; nf < 8; nf++)
                mma_bf(s[nf], aq[kc], bq[nf]);
        }

        float rm0 = -CUDART_INF_F, rm1 = -CUDART_INF_F;
#pragma unroll
        for (int nf = 0; nf < 8; nf++) {
            rm0 = fmaxf(rm0, fmaxf(s[nf][0], s[nf][1]));
            rm1 = fmaxf(rm1, fmaxf(s[nf][2], s[nf][3]));
        }
        rm0 = fmaxf(rm0, __shfl_xor_sync(0xffffffffu, rm0, 1));
        rm0 = fmaxf(rm0, __shfl_xor_sync(0xffffffffu, rm0, 2));
        rm1 = fmaxf(rm1, __shfl_xor_sync(0xffffffffu, rm1, 1));
        rm1 = fmaxf(rm1, __shfl_xor_sync(0xffffffffu, rm1, 2));
        float mn0 = fmaxf(m0, rm0), mn1 = fmaxf(m1, rm1);
        float sc0 = __expf(m0 - mn0), sc1 = __expf(m1 - mn1);
        m0 = mn0; m1 = mn1;
        float rs0 = 0.f, rs1 = 0.f;
#pragma unroll
        for (int nf = 0; nf < 8; nf++) {
            s[nf][0] = __expf(s[nf][0] - mn0);
            s[nf][1] = __expf(s[nf][1] - mn0);
            s[nf][2] = __expf(s[nf][2] - mn1);
            s[nf][3] = __expf(s[nf][3] - mn1);
            rs0 += s[nf][0] + s[nf][1];
            rs1 += s[nf][2] + s[nf][3];
        }
        rs0 += __shfl_xor_sync(0xffffffffu, rs0, 1);
        rs0 += __shfl_xor_sync(0xffffffffu, rs0, 2);
        rs1 += __shfl_xor_sync(0xffffffffu, rs1, 1);
        rs1 += __shfl_xor_sync(0xffffffffu, rs1, 2);
        l0 = l0 * sc0 + rs0;
        l1 = l1 * sc1 + rs1;
#pragma unroll
        for (int nf = 0; nf < 8; nf++) {
            o_acc[nf][0] *= sc0; o_acc[nf][1] *= sc0;
            o_acc[nf][2] *= sc1; o_acc[nf][3] *= sc1;
        }

        // P -> fp16 A-fragments (4 k16 chunks), single chain
        uint32_t Ahi[4][4];
#pragma unroll
        for (int kc = 0; kc < 4; kc++) {
            int f0 = 2*kc, f1 = 2*kc + 1;
            Ahi[kc][0] = pkhf(s[f0][0], s[f0][1]);
            Ahi[kc][1] = pkhf(s[f0][2], s[f0][3]);
            Ahi[kc][2] = pkhf(s[f1][0], s[f1][1]);
            Ahi[kc][3] = pkhf(s[f1][2], s[f1][3]);
        }

        // PV: o += Phi * Vhi (fp16 single chain)
#pragma unroll
        for (int kc = 0; kc < 4; kc++) {
            uint32_t bvh[8][2];
#pragma unroll
            for (int np = 0; np < 4; np++)
                ldsm_x4(bvh[2*np][0], bvh[2*np][1], bvh[2*np+1][0], bvh[2*np+1][1],
                        vd + ((np*16 + brow) * LDV + kc*16 + bcol8) * 2);
#pragma unroll
            for (int nf = 0; nf < 8; nf++)
                mma_hf(o_acc[nf], Ahi[kc], bvh[nf]);
        }
        __syncthreads();
    }

    // epilogue: write fp16 [hi|lo] rows of g_o2 (K = 2048)
    float inv0 = 1.0f / l0, inv1 = 1.0f / l1;
    int r0 = q0 + wid * 16 + (lane >> 2);
    int r1 = r0 + 8;
    __half* row0 = g_o2 + (size_t)(b * Tc + r0) * 2048;
    __half* row1 = g_o2 + (size_t)(b * Tc + r1) * 2048;
#pragma unroll
    for (int nf = 0; nf < 8; nf++) {
        int n = h * HDc + nf * 8 + 2 * (lane & 3);
        float v00 = o_acc[nf][0] * inv0, v01 = o_acc[nf][1] * inv0;
        float v10 = o_acc[nf][2] * inv1, v11 = o_acc[nf][3] * inv1;
        float e00 = hfr(v00), e01 = hfr(v01), e10 = hfr(v10), e11 = hfr(v11);
        *(uint32_t*)(row0 + n)        = pkhf(e00, e01);
        *(uint32_t*)(row0 + 1024 + n) = pkhf(v00 - e00, v01 - e01);
        *(uint32_t*)(row1 + n)        = pkhf(e10, e11);
        *(uint32_t*)(row1 + 1024 + n) = pkhf(v10 - e10, v11 - e11);
    }
}

// ---------------------------------------------------------------------------
extern "C" void kernel_launch(void* const* d_in, const int* in_sizes, int n_in,
                              void* d_out, int out_size) {
    const float* x   = (const float*)d_in[0];
    const float* Wq  = (const float*)d_in[1];
    const float* bq  = (const float*)d_in[2];
    const float* Wk  = (const float*)d_in[3];
    const float* bk  = (const float*)d_in[4];
    const float* Wv  = (const float*)d_in[5];
    const float* bv  = (const float*)d_in[6];
    const float* Wo  = (const float*)d_in[7];
    const float* bo  = (const float*)d_in[8];
    const float* A   = (const float*)d_in[9];
    const float* ll  = (const float*)d_in[10];
    float* out = (float*)d_out;

    cudaFuncSetAttribute(gemm_tc<0>, cudaFuncAttributeMaxDynamicSharedMemorySize, SMEM_DYN);
    cudaFuncSetAttribute(gemm_tc<1>, cudaFuncAttributeMaxDynamicSharedMemorySize, SMEM_DYN);
    cudaFuncSetAttribute(attn_tc, cudaFuncAttributeMaxDynamicSharedMemorySize, ASMEM);

    void *x2, *x2h, *w2qk, *w2vh, *w2oh, *o2h;
    float* bqk;
    cudaGetSymbolAddress(&x2,    g_x2);
    cudaGetSymbolAddress(&x2h,   g_x2h);
    cudaGetSymbolAddress(&w2qk,  g_w2);
    cudaGetSymbolAddress(&w2vh,  g_w2v);
    cudaGetSymbolAddress(&w2oh,  g_w2o);
    cudaGetSymbolAddress(&o2h,   g_o2);
    cudaGetSymbolAddress((void**)&bqk, g_bqk);

    split_kernel<<<(Mc*Dc/2 + 255)/256, 256>>>(x, (__nv_bfloat16*)x2, Mc, 0);
    split_xh<<<(Mc*Dc/2 + 255)/256, 256>>>(x);
    split_kernel<<<(Dc*Dc/2 + 255)/256, 256>>>(Wq, (__nv_bfloat16*)w2qk, Dc, 1);
    split_kernel<<<(Dc*Dc/2 + 255)/256, 256>>>(
        Wk, (__nv_bfloat16*)w2qk + (size_t)Dc*KTOT, Dc, 1);
    wsplit_h<<<(Dc*Dc + 255)/256, 256>>>(Wv, (__half*)w2vh);
    wsplit_h<<<(Dc*Dc + 255)/256, 256>>>(Wo, (__half*)w2oh);
    bias_concat<<<8, 256>>>(bq, bk);

    // fused QK: N = 2048, bf16 3-product, K=3072
    gemm_tc<0><<<dim3(Mc/BM, 2*Dc/BN), 256, SMEM_DYN>>>(x2, w2qk, bqk, nullptr, 0, KTOT);
    // V: fp16 2-product, K=2048
    gemm_tc<1><<<dim3(Mc/BM, Dc/BN), 256, SMEM_DYN>>>(x2h, w2vh, bv, nullptr, 2, 2048);

    gdiag_kernel<<<4, 256>>>(A, ll);
    ksum2_kernel<<<Bc*Hc, 256>>>();
    sgprep_kernel<<<(Bc*Hc*Tc*HDc + 255)/256, 256>>>();

    attn_tc<<<dim3(Tc / AT_M, Bc * Hc), 256, ASMEM>>>();

    // final projection: fp16 2-product, K=2048
    gemm_tc<1><<<dim3(Mc/BM, Dc/BN), 256, SMEM_DYN>>>(o2h, w2oh, bo, out, 1, 2048);
}

// round 8
// speedup vs baseline: 1.4782x; 1.1987x over previous
#include <cuda_runtime.h>
#include <cuda_bf16.h>
#include <cuda_fp16.h>
#include <math_constants.h>
#include <cstdint>

#define Bc 2
#define Tc 2048
#define Dc 1024
#define Hc 16
#define HDc 64
#define Mc (Bc*Tc)

#define KTOT 3072          // tripled K for split-bf16 3-product GEMM
#define BM 128
#define BN 256
#define BK 32
#define LDS_ROW 40
#define A_STG (BM*LDS_ROW*2)              // 10240
#define B_STG (BN*LDS_ROW*2)              // 20480
#define STG_BYTES (A_STG+B_STG)           // 30720
#define STAGES 4
#define SMEM_DYN (STAGES*STG_BYTES)       // 122880

// attention tiling
#define AT_M 128
#define LDSA 200
#define LDV  72
#define SG_BYTES_A (128*LDSA*2)           // 51200
#define K2STG (64*LDSA*2)                 // 25600
#define VTSTG (64*LDV*2)                  // 9216
#define ASMEM (SG_BYTES_A + 2*K2STG + 2*VTSTG)  // 120832

// ---------------- scratch (device globals; no runtime allocation) ----------
__device__ __align__(16) float g_q[Bc*Hc*Tc*HDc];      // (b,h,t,hd) fp32
__device__ __align__(16) float g_ksum[Bc*Hc*HDc];
__device__ __align__(16) float g_gdiag[Hc*HDc];
__device__ __align__(16) float g_bqk[2*Dc];
__device__ __align__(16) __nv_bfloat16 g_x2[Mc*KTOT];        // [hi|hi|lo] of x (bf16)
__device__ __align__(16) __half g_xh[Mc*1024];               // fp16(x)
__device__ __align__(16) __nv_bfloat16 g_w2[2][Dc*KTOT];     // [hi|lo|hi] Wq,Wk
__device__ __align__(16) __half g_wv[Dc*1024];               // fp16(Wv)
__device__ __align__(16) __half g_wo[Dc*1024];               // fp16(Wo)
__device__ __align__(16) __half g_o2h[Mc*1024];              // fp16 attn out
__device__ __align__(16) __nv_bfloat16 g_k2[Bc*Hc*Tc*192];   // [hi|lo|hi] key rows
__device__ __align__(16) __half g_v2t[Bc*Hc*HDc*Tc];         // [bh][d][t] fp16 V^T

// ---------------- PTX helpers ----------------------------------------------
__device__ __forceinline__ uint32_t smem_u32(const void* p) {
    uint32_t a;
    asm("{ .reg .u64 t; cvta.to.shared.u64 t, %1; cvt.u32.u64 %0, t; }" : "=r"(a) : "l"(p));
    return a;
}
#define CP_ASYNC16(sm, gm) \
    asm volatile("cp.async.cg.shared.global [%0], [%1], 16;" :: "r"(sm), "l"(gm))
#define CP_COMMIT() asm volatile("cp.async.commit_group;" ::: "memory")
#define CP_WAIT(n)  asm volatile("cp.async.wait_group %0;" :: "n"(n) : "memory")

__device__ __forceinline__ void ldsm_x4(uint32_t& r0, uint32_t& r1,
                                        uint32_t& r2, uint32_t& r3, uint32_t addr) {
    asm volatile("ldmatrix.sync.aligned.m8n8.x4.shared.b16 {%0,%1,%2,%3}, [%4];"
                 : "=r"(r0), "=r"(r1), "=r"(r2), "=r"(r3) : "r"(addr));
}
__device__ __forceinline__ void mma_bf(float* c, const uint32_t* a, const uint32_t* b) {
    asm volatile(
        "mma.sync.aligned.m16n8k16.row.col.f32.bf16.bf16.f32 "
        "{%0,%1,%2,%3}, {%4,%5,%6,%7}, {%8,%9}, {%0,%1,%2,%3};"
        : "+f"(c[0]), "+f"(c[1]), "+f"(c[2]), "+f"(c[3])
        : "r"(a[0]), "r"(a[1]), "r"(a[2]), "r"(a[3]), "r"(b[0]), "r"(b[1]));
}
__device__ __forceinline__ void mma_hf(float* c, const uint32_t* a, const uint32_t* b) {
    asm volatile(
        "mma.sync.aligned.m16n8k16.row.col.f32.f16.f16.f32 "
        "{%0,%1,%2,%3}, {%4,%5,%6,%7}, {%8,%9}, {%0,%1,%2,%3};"
        : "+f"(c[0]), "+f"(c[1]), "+f"(c[2]), "+f"(c[3])
        : "r"(a[0]), "r"(a[1]), "r"(a[2]), "r"(a[3]), "r"(b[0]), "r"(b[1]));
}
__device__ __forceinline__ uint32_t pkhf(float lo, float hi) {
    uint32_t r;
    asm("cvt.rn.f16x2.f32 %0, %1, %2;" : "=r"(r) : "f"(hi), "f"(lo));
    return r;
}

// ---------------------------------------------------------------------------
// One prep kernel: x -> bf16 triple + fp16 plane; Wq/Wk -> bf16 triples;
// Wv/Wo -> fp16 planes; bias concat; gdiag.
// ---------------------------------------------------------------------------
__global__ void prep_all(const float* __restrict__ x,
                         const float* __restrict__ Wq, const float* __restrict__ Wk,
                         const float* __restrict__ Wv, const float* __restrict__ Wo,
                         const float* __restrict__ bq, const float* __restrict__ bk,
                         const float* __restrict__ A, const float* __restrict__ ll) {
    int i = blockIdx.x * blockDim.x + threadIdx.x;
    const int N0 = Mc * 512, NW = Dc * 512;
    if (i < N0) {                               // x: triple + fp16
        float2 v = ((const float2*)x)[i];
        int r = i >> 9, c2 = i & 511;
        __nv_bfloat162 hi, lo;
        hi.x = __float2bfloat16(v.x); hi.y = __float2bfloat16(v.y);
        lo.x = __float2bfloat16(v.x - __bfloat162float(hi.x));
        lo.y = __float2bfloat16(v.y - __bfloat162float(hi.y));
        __nv_bfloat162* d = (__nv_bfloat162*)(g_x2 + (size_t)r * KTOT);
        d[c2] = hi; d[512 + c2] = hi; d[1024 + c2] = lo;
        __half2 h; h.x = __float2half_rn(v.x); h.y = __float2half_rn(v.y);
        ((__half2*)(g_xh + (size_t)r * 1024))[c2] = h;
        return;
    }
    i -= N0;
    if (i < 2 * NW) {                           // Wq / Wk bf16 triple [hi|lo|hi]
        const float* W = (i < NW) ? Wq : Wk;
        __nv_bfloat16* dst = (i < NW) ? g_w2[0] : g_w2[1];
        int j = (i < NW) ? i : i - NW;
        float2 v = ((const float2*)W)[j];
        int r = j >> 9, c2 = j & 511;
        __nv_bfloat162 hi, lo;
        hi.x = __float2bfloat16(v.x); hi.y = __float2bfloat16(v.y);
        lo.x = __float2bfloat16(v.x - __bfloat162float(hi.x));
        lo.y = __float2bfloat16(v.y - __bfloat162float(hi.y));
        __nv_bfloat162* d = (__nv_bfloat162*)(dst + (size_t)r * KTOT);
        d[c2] = hi; d[512 + c2] = lo; d[1024 + c2] = hi;
        return;
    }
    i -= 2 * NW;
    if (i < 2 * NW) {                           // Wv / Wo fp16 plane
        const float* W = (i < NW) ? Wv : Wo;
        __half* dst = (i < NW) ? g_wv : g_wo;
        int j = (i < NW) ? i : i - NW;
        float2 v = ((const float2*)W)[j];
        int r = j >> 9, c2 = j & 511;
        __half2 h; h.x = __float2half_rn(v.x); h.y = __float2half_rn(v.y);
        ((__half2*)(dst + (size_t)r * 1024))[c2] = h;
        return;
    }
    i -= 2 * NW;
    if (i < 2 * Dc) {                           // bias concat
        g_bqk[i] = (i < Dc) ? bq[i] : bk[i - Dc];
        return;
    }
    i -= 2 * Dc;
    if (i < Hc * HDc) {                         // gdiag
        int h = i >> 6, d = i & 63;
        float s = expf(ll[h]);
#pragma unroll
        for (int r = 0; r < 16; r++) {
            float a = A[(h * 16 + r) * HDc + d];
            s = fmaf(a, a, s);
        }
        g_gdiag[i] = s;
    }
}
#define PREP_TOTAL (Mc*512 + 4*(Dc*512) + 2*Dc + Hc*HDc)

// ---------------------------------------------------------------------------
// GEMM body: tile 128x256, warp 64x64, BK=32, 4-stage cp.async.
// mode 0: QK (n0>>10: q fp32 / k triple); mode 1: -> Yext; mode 2: V plane.
// ---------------------------------------------------------------------------
template<int FP16M>
__device__ __forceinline__ void gemm_body(
    uint32_t base, const char* gAb, const char* gWb,
    const float* __restrict__ bias, float* __restrict__ Yext,
    int mode, int ktot, int m0, int n0)
{
    int tid = threadIdx.x, wid = tid >> 5, lane = tid & 31;
    int wm = wid & 1, wn = wid >> 1;

    const char* gA = gAb + (size_t)m0 * ktot * 2;
    const char* gW = gWb + (size_t)n0 * ktot * 2;
    size_t kstride = (size_t)ktot * 2;

    auto load_chunk = [&](int c) {
        uint32_t sa = base + (c % STAGES) * STG_BYTES;
        uint32_t sb = sa + A_STG;
        size_t k0 = (size_t)c * (BK * 2);
#pragma unroll
        for (int it = 0; it < 2; it++) {
            int ch = tid + it * 256;
            int r = ch >> 2, off = (ch & 3) * 16;
            CP_ASYNC16(sa + r * (LDS_ROW*2) + off, gA + r * kstride + k0 + off);
        }
#pragma unroll
        for (int it = 0; it < 4; it++) {
            int ch = tid + it * 256;
            int r = ch >> 2, off = (ch & 3) * 16;
            CP_ASYNC16(sb + r * (LDS_ROW*2) + off, gW + r * kstride + k0 + off);
        }
        CP_COMMIT();
    };

    float acc[4][8][4];
#pragma unroll
    for (int i = 0; i < 4; i++)
#pragma unroll
        for (int j = 0; j < 8; j++)
#pragma unroll
            for (int l = 0; l < 4; l++) acc[i][j][l] = 0.f;

    load_chunk(0);
    load_chunk(1);
    load_chunk(2);

    int a_row = wm * 64 + (lane & 15);
    int a_col8 = (lane >> 4) * 8;
    int b_row = wn * 64 + (lane & 7) + ((lane >> 4) << 3);
    int b_col8 = ((lane >> 3) & 1) * 8;
    int nk = ktot / BK;

#pragma unroll 1
    for (int i = 0; i < nk; i++) {
        CP_WAIT(STAGES - 2);
        __syncthreads();
        if (i + STAGES - 1 < nk) load_chunk(i + STAGES - 1);

        uint32_t sa = base + (i % STAGES) * STG_BYTES;
        uint32_t sb = sa + A_STG;
#pragma unroll
        for (int kk = 0; kk < 2; kk++) {
            uint32_t a[4][4], b[8][2];
#pragma unroll
            for (int mf = 0; mf < 4; mf++)
                ldsm_x4(a[mf][0], a[mf][1], a[mf][2], a[mf][3],
                        sa + ((a_row + mf*16) * LDS_ROW + kk*16 + a_col8) * 2);
#pragma unroll
            for (int np = 0; np < 4; np++)
                ldsm_x4(b[2*np][0], b[2*np][1], b[2*np+1][0], b[2*np+1][1],
                        sb + ((b_row + np*16) * LDS_ROW + kk*16 + b_col8) * 2);
#pragma unroll
            for (int mf = 0; mf < 4; mf++)
#pragma unroll
                for (int nf = 0; nf < 8; nf++) {
                    if (FP16M) mma_hf(acc[mf][nf], a[mf], b[nf]);
                    else       mma_bf(acc[mf][nf], a[mf], b[nf]);
                }
        }
    }

    int proj = n0 >> 10;
#pragma unroll
    for (int mf = 0; mf < 4; mf++) {
#pragma unroll
        for (int nf = 0; nf < 8; nf++) {
            int m = m0 + wm*64 + mf*16 + (lane >> 2);
            int n = n0 + wn*64 + nf*8 + 2*(lane & 3);
            float b0 = bias[n], b1 = bias[n+1];
#pragma unroll
            for (int half = 0; half < 2; half++) {
                int mm = m + half * 8;
                float v0 = acc[mf][nf][half*2+0] + b0;
                float v1 = acc[mf][nf][half*2+1] + b1;
                int bb = mm >> 11, t = mm & 2047;
                int nn = n & 1023;
                int h = nn >> 6, d = nn & 63;
                int bh = bb * Hc + h;
                if (mode == 1) {
                    *(float2*)(Yext + (size_t)mm * Dc + n) = make_float2(v0, v1);
                } else if (mode == 2) {
                    __half* pbase = g_v2t + (size_t)bh * HDc * Tc;
                    pbase[(size_t)d * Tc + t]     = __float2half_rn(v0);
                    pbase[(size_t)(d+1) * Tc + t] = __float2half_rn(v1);
                } else if (proj == 0) {
                    *(float2*)(g_q + ((size_t)bh * Tc + t) * HDc + d) =
                        make_float2(v0, v1);
                } else {
                    __nv_bfloat16 h0 = __float2bfloat16(v0);
                    __nv_bfloat16 l0 = __float2bfloat16(v0 - __bfloat162float(h0));
                    __nv_bfloat16 h1 = __float2bfloat16(v1);
                    __nv_bfloat16 l1 = __float2bfloat16(v1 - __bfloat162float(h1));
                    __nv_bfloat16* row = g_k2 + ((size_t)bh * Tc + t) * 192;
                    row[d] = h0;   row[d+1] = h1;
                    row[64+d] = l0; row[64+d+1] = l1;
                    row[128+d] = h0; row[128+d+1] = h1;
                }
            }
        }
    }
}

// fused QKV: y<8 -> QK bf16 3-product (K=3072); y>=8 -> V fp16 (K=1024)
__global__ __launch_bounds__(256)
void qkv_fused(const float* __restrict__ bv) {
    extern __shared__ __align__(16) char dsmem[];
    uint32_t base = smem_u32(dsmem);
    int by = blockIdx.y;
    if (by < 8)
        gemm_body<0>(base, (const char*)g_x2, (const char*)g_w2,
                     g_bqk, nullptr, 0, KTOT, blockIdx.x * BM, by * 256);
    else
        gemm_body<1>(base, (const char*)g_xh, (const char*)g_wv,
                     bv, nullptr, 2, 1024, blockIdx.x * BM, (by - 8) * 256);
}

// final projection: out = o2h @ Wo^T + bo  (fp16 single product, K=1024)
__global__ __launch_bounds__(256)
void gemm_o(const float* __restrict__ bo, float* __restrict__ out) {
    extern __shared__ __align__(16) char dsmem[];
    uint32_t base = smem_u32(dsmem);
    gemm_body<1>(base, (const char*)g_o2h, (const char*)g_wo,
                 bo, out, 1, 1024, blockIdx.x * BM, blockIdx.y * 256);
}

// ---------------------------------------------------------------------------
__global__ __launch_bounds__(256) void ksum2_kernel() {
    __shared__ float red[256];
    int bh = blockIdx.x;
    int d = threadIdx.x & 63, chunk = threadIdx.x >> 6;
    const __nv_bfloat16* base = g_k2 + (size_t)bh * Tc * 192;
    float s = 0.f;
    for (int t = chunk * 512; t < (chunk + 1) * 512; t++) {
        const __nv_bfloat16* row = base + (size_t)t * 192;
        s += __bfloat162float(row[d]) + __bfloat162float(row[64 + d]);
    }
    red[threadIdx.x] = s;
    __syncthreads();
    if (chunk == 0) {
        float tot = red[d] + red[64+d] + red[128+d] + red[192+d];
        g_ksum[bh * HDc + d] = tot;
    }
}

// ---------------------------------------------------------------------------
// Tensor-core flash attention. Sg computed in-kernel from g_q (bf16 triple
// into smem). QK bf16 3-product (K=192); PV fp16 single chain; epilogue
// writes fp16 plane g_o2h.
// ---------------------------------------------------------------------------
__global__ __launch_bounds__(256, 1)
void attn_tc() {
    extern __shared__ __align__(16) char asmem[];
    uint32_t sgs = smem_u32(asmem);
    uint32_t k2s = sgs + SG_BYTES_A;
    uint32_t vts = k2s + 2 * K2STG;
    __nv_bfloat16* sg_sm = (__nv_bfloat16*)asmem;

    int tid = threadIdx.x, wid = tid >> 5, lane = tid & 31;
    int bh = blockIdx.y, h = bh & 15, b = bh >> 4;
    int q0 = blockIdx.x * AT_M;

    const float*         q_g = g_q   + ((size_t)bh * Tc + q0) * HDc;
    const __nv_bfloat16* k_g = g_k2  + (size_t)bh * Tc * 192;
    const __half*        v_g = g_v2t + (size_t)bh * HDc * Tc;
    const float*         ks  = g_ksum + bh * HDc;
    const float*         gd  = g_gdiag + h * HDc;

    auto load_tile = [&](int ti) {
        int st = ti & 1;
        int j0 = ti * 64;
        uint32_t kd = k2s + st * K2STG;
        uint32_t vd = vts + st * VTSTG;
#pragma unroll
        for (int it = 0; it < 6; it++) {          // K: 64 x 192 bf16
            int id = tid + it * 256;
            int r = id / 24, c = id % 24;
            CP_ASYNC16(kd + r * (LDSA*2) + c * 16,
                       (const char*)(k_g + (size_t)(j0 + r) * 192 + c * 8));
        }
#pragma unroll
        for (int it = 0; it < 2; it++) {          // V^T: 64 x 64 fp16
            int id = tid + it * 256;
            int r = id >> 3, c = id & 7;
            CP_ASYNC16(vd + r * (LDV*2) + c * 16,
                       (const char*)(v_g + (size_t)r * Tc + j0 + c * 8));
        }
        CP_COMMIT();
    };

    load_tile(0);

    // compute Sg tile in-kernel: [hi|hi|lo] rows of LDSA
    for (int idx = tid; idx < 128 * 64; idx += 256) {
        int r = idx >> 6, d = idx & 63;
        float sg = (2048.0f * q_g[r * HDc + d] - ks[d]) * gd[d];
        __nv_bfloat16 hi = __float2bfloat16(sg);
        __nv_bfloat16 lo = __float2bfloat16(sg - __bfloat162float(hi));
        __nv_bfloat16* row = sg_sm + r * LDSA;
        row[d] = hi; row[64 + d] = hi; row[128 + d] = lo;
    }
    __syncthreads();

    uint32_t aq[12][4];
    {
        int arow = wid * 16 + (lane & 15);
        int acol = (lane >> 4) * 8;
#pragma unroll
        for (int kc = 0; kc < 12; kc++)
            ldsm_x4(aq[kc][0], aq[kc][1], aq[kc][2], aq[kc][3],
                    sgs + (arow * LDSA + kc * 16 + acol) * 2);
    }

    float o_acc[8][4];
#pragma unroll
    for (int nf = 0; nf < 8; nf++)
#pragma unroll
        for (int l = 0; l < 4; l++) o_acc[nf][l] = 0.f;
    float m0 = -CUDART_INF_F, m1 = -CUDART_INF_F, l0 = 0.f, l1 = 0.f;

    int brow = (lane & 7) + ((lane >> 4) << 3);
    int bcol8 = ((lane >> 3) & 1) * 8;

#pragma unroll 1
    for (int ti = 0; ti < 32; ti++) {
        if (ti + 1 < 32) { load_tile(ti + 1); CP_WAIT(1); }
        else CP_WAIT(0);
        __syncthreads();
        int st = ti & 1;
        uint32_t kd = k2s + st * K2STG;
        uint32_t vd = vts + st * VTSTG;

        float s[8][4];
#pragma unroll
        for (int nf = 0; nf < 8; nf++)
#pragma unroll
            for (int l = 0; l < 4; l++) s[nf][l] = 0.f;
#pragma unroll
        for (int kc = 0; kc < 12; kc++) {
            uint32_t bq[8][2];
#pragma unroll
            for (int np = 0; np < 4; np++)
                ldsm_x4(bq[2*np][0], bq[2*np][1], bq[2*np+1][0], bq[2*np+1][1],
                        kd + ((np*16 + brow) * LDSA + kc*16 + bcol8) * 2);
#pragma unroll
            for (int nf = 0; nf < 8; nf++)
                mma_bf(s[nf], aq[kc], bq[nf]);
        }

        float rm0 = -CUDART_INF_F, rm1 = -CUDART_INF_F;
#pragma unroll
        for (int nf = 0; nf < 8; nf++) {
            rm0 = fmaxf(rm0, fmaxf(s[nf][0], s[nf][1]));
            rm1 = fmaxf(rm1, fmaxf(s[nf][2], s[nf][3]));
        }
        rm0 = fmaxf(rm0, __shfl_xor_sync(0xffffffffu, rm0, 1));
        rm0 = fmaxf(rm0, __shfl_xor_sync(0xffffffffu, rm0, 2));
        rm1 = fmaxf(rm1, __shfl_xor_sync(0xffffffffu, rm1, 1));
        rm1 = fmaxf(rm1, __shfl_xor_sync(0xffffffffu, rm1, 2));
        float mn0 = fmaxf(m0, rm0), mn1 = fmaxf(m1, rm1);
        float sc0 = __expf(m0 - mn0), sc1 = __expf(m1 - mn1);
        m0 = mn0; m1 = mn1;
        float rs0 = 0.f, rs1 = 0.f;
#pragma unroll
        for (int nf = 0; nf < 8; nf++) {
            s[nf][0] = __expf(s[nf][0] - mn0);
            s[nf][1] = __expf(s[nf][1] - mn0);
            s[nf][2] = __expf(s[nf][2] - mn1);
            s[nf][3] = __expf(s[nf][3] - mn1);
            rs0 += s[nf][0] + s[nf][1];
            rs1 += s[nf][2] + s[nf][3];
        }
        rs0 += __shfl_xor_sync(0xffffffffu, rs0, 1);
        rs0 += __shfl_xor_sync(0xffffffffu, rs0, 2);
        rs1 += __shfl_xor_sync(0xffffffffu, rs1, 1);
        rs1 += __shfl_xor_sync(0xffffffffu, rs1, 2);
        l0 = l0 * sc0 + rs0;
        l1 = l1 * sc1 + rs1;
#pragma unroll
        for (int nf = 0; nf < 8; nf++) {
            o_acc[nf][0] *= sc0; o_acc[nf][1] *= sc0;
            o_acc[nf][2] *= sc1; o_acc[nf][3] *= sc1;
        }

        uint32_t Ahi[4][4];
#pragma unroll
        for (int kc = 0; kc < 4; kc++) {
            int f0 = 2*kc, f1 = 2*kc + 1;
            Ahi[kc][0] = pkhf(s[f0][0], s[f0][1]);
            Ahi[kc][1] = pkhf(s[f0][2], s[f0][3]);
            Ahi[kc][2] = pkhf(s[f1][0], s[f1][1]);
            Ahi[kc][3] = pkhf(s[f1][2], s[f1][3]);
        }

#pragma unroll
        for (int kc = 0; kc < 4; kc++) {
            uint32_t bvh[8][2];
#pragma unroll
            for (int np = 0; np < 4; np++)
                ldsm_x4(bvh[2*np][0], bvh[2*np][1], bvh[2*np+1][0], bvh[2*np+1][1],
                        vd + ((np*16 + brow) * LDV + kc*16 + bcol8) * 2);
#pragma unroll
            for (int nf = 0; nf < 8; nf++)
                mma_hf(o_acc[nf], Ahi[kc], bvh[nf]);
        }
        __syncthreads();
    }

    // epilogue: fp16 plane
    float inv0 = 1.0f / l0, inv1 = 1.0f / l1;
    int r0 = q0 + wid * 16 + (lane >> 2);
    int r1 = r0 + 8;
    __half* row0 = g_o2h + (size_t)(b * Tc + r0) * 1024;
    __half* row1 = g_o2h + (size_t)(b * Tc + r1) * 1024;
#pragma unroll
    for (int nf = 0; nf < 8; nf++) {
        int n = h * HDc + nf * 8 + 2 * (lane & 3);
        *(uint32_t*)(row0 + n) = pkhf(o_acc[nf][0] * inv0, o_acc[nf][1] * inv0);
        *(uint32_t*)(row1 + n) = pkhf(o_acc[nf][2] * inv1, o_acc[nf][3] * inv1);
    }
}

// ---------------------------------------------------------------------------
extern "C" void kernel_launch(void* const* d_in, const int* in_sizes, int n_in,
                              void* d_out, int out_size) {
    const float* x   = (const float*)d_in[0];
    const float* Wq  = (const float*)d_in[1];
    const float* bq  = (const float*)d_in[2];
    const float* Wk  = (const float*)d_in[3];
    const float* bk  = (const float*)d_in[4];
    const float* Wv  = (const float*)d_in[5];
    const float* bv  = (const float*)d_in[6];
    const float* Wo  = (const float*)d_in[7];
    const float* bo  = (const float*)d_in[8];
    const float* A   = (const float*)d_in[9];
    const float* ll  = (const float*)d_in[10];
    float* out = (float*)d_out;

    cudaFuncSetAttribute(qkv_fused, cudaFuncAttributeMaxDynamicSharedMemorySize, SMEM_DYN);
    cudaFuncSetAttribute(gemm_o,    cudaFuncAttributeMaxDynamicSharedMemorySize, SMEM_DYN);
    cudaFuncSetAttribute(attn_tc,   cudaFuncAttributeMaxDynamicSharedMemorySize, ASMEM);

    prep_all<<<(PREP_TOTAL + 255)/256, 256>>>(x, Wq, Wk, Wv, Wo, bq, bk, A, ll);

    // fused QK (bf16 3-product) + V (fp16 single product)
    qkv_fused<<<dim3(Mc/BM, 12), 256, SMEM_DYN>>>(bv);

    ksum2_kernel<<<Bc*Hc, 256>>>();

    attn_tc<<<dim3(Tc / AT_M, Bc * Hc), 256, ASMEM>>>();

    gemm_o<<<dim3(Mc/BM, Dc/BN), 256, SMEM_DYN>>>(bo, out);
}